// round 6
// baseline (speedup 1.0000x reference)
#include <cuda_runtime.h>
#include <cuda_bf16.h>
#include <cstdint>
#include <math.h>

#define D_MODEL 1024
#define DFF     4096
#define SEQ     2048
#define BATCH   2
#define NTOK    (SEQ*BATCH)      // 4096
#define NHEADS  16
#define HDIM    64
#define QKV_W   3072             // fused qkv width

typedef __nv_bfloat16 bf16;

// ---------------- scratch (device globals: allocation-free rule) ----------------
__device__ bf16  g_lnH [NTOK*(size_t)D_MODEL];
__device__ bf16  g_lnL [NTOK*(size_t)D_MODEL];
__device__ float g_qkv [NTOK*(size_t)QKV_W];
__device__ bf16  g_ctxH[NTOK*(size_t)D_MODEL];
__device__ bf16  g_ctxL[NTOK*(size_t)D_MODEL];
__device__ float g_h   [NTOK*(size_t)D_MODEL];
__device__ bf16  g_f1H [NTOK*(size_t)DFF];
__device__ bf16  g_f1L [NTOK*(size_t)DFF];
__device__ bf16  g_wqkvTH[(size_t)QKV_W*D_MODEL];
__device__ bf16  g_wqkvTL[(size_t)QKV_W*D_MODEL];
__device__ bf16  g_woTH  [(size_t)D_MODEL*D_MODEL];
__device__ bf16  g_woTL  [(size_t)D_MODEL*D_MODEL];
__device__ bf16  g_w1TH  [(size_t)DFF*D_MODEL];
__device__ bf16  g_w1TL  [(size_t)DFF*D_MODEL];
__device__ bf16  g_w2TH  [(size_t)D_MODEL*DFF];
__device__ bf16  g_w2TL  [(size_t)D_MODEL*DFF];

// ================= helpers =================
__device__ __forceinline__ uint32_t smem_u32(const void* p) {
    uint32_t a;
    asm("{ .reg .u64 t; cvta.to.shared.u64 t, %1; cvt.u32.u64 %0, t; }" : "=r"(a) : "l"(p));
    return a;
}

#define LDSM_X4(r0,r1,r2,r3,a) \
    asm volatile("ldmatrix.sync.aligned.m8n8.x4.shared.b16 {%0,%1,%2,%3}, [%4];" \
        : "=r"(r0), "=r"(r1), "=r"(r2), "=r"(r3) : "r"(a))
#define LDSM_X4_T(r0,r1,r2,r3,a) \
    asm volatile("ldmatrix.sync.aligned.m8n8.x4.trans.shared.b16 {%0,%1,%2,%3}, [%4];" \
        : "=r"(r0), "=r"(r1), "=r"(r2), "=r"(r3) : "r"(a))

#define MMA_BF16(c, a, b0, b1) \
    asm volatile("mma.sync.aligned.m16n8k16.row.col.f32.bf16.bf16.f32 " \
        "{%0,%1,%2,%3}, {%4,%5,%6,%7}, {%8,%9}, {%0,%1,%2,%3};" \
        : "+f"((c)[0]), "+f"((c)[1]), "+f"((c)[2]), "+f"((c)[3]) \
        : "r"((a)[0]), "r"((a)[1]), "r"((a)[2]), "r"((a)[3]), "r"(b0), "r"(b1))

__device__ __forceinline__ uint32_t pack_bf2(bf16 a, bf16 b) {
    __nv_bfloat162 t; t.x = a; t.y = b;
    return *(uint32_t*)&t;
}
__device__ __forceinline__ uint32_t pack_hi(float a, float b) {
    return pack_bf2(__float2bfloat16(a), __float2bfloat16(b));
}
__device__ __forceinline__ uint32_t pack_lo(float a, float b) {
    bf16 ha = __float2bfloat16(a), hb = __float2bfloat16(b);
    return pack_bf2(__float2bfloat16(a - __bfloat162float(ha)),
                    __float2bfloat16(b - __bfloat162float(hb)));
}

__device__ __forceinline__ void cp16(uint32_t dst, const void* src) {
    asm volatile("cp.async.cg.shared.global [%0], [%1], 16;" :: "r"(dst), "l"(src));
}

// ================= weight transpose+split: in[R,C] fp32 -> outH/outL[C,R] bf16 ===========
__global__ void __launch_bounds__(256) transpose_split_kernel(
    const float* __restrict__ in, bf16* __restrict__ outH, bf16* __restrict__ outL,
    int R, int C)
{
    __shared__ float tile[32][33];
    int tx = threadIdx.x, ty = threadIdx.y;
    int x = blockIdx.x * 32 + tx;
    int y0 = blockIdx.y * 32;
#pragma unroll
    for (int i = ty; i < 32; i += 8)
        tile[i][tx] = in[(size_t)(y0 + i) * C + x];
    __syncthreads();
    int xo = y0 + tx;
    int y1 = blockIdx.x * 32;
#pragma unroll
    for (int i = ty; i < 32; i += 8) {
        float v = tile[tx][i];
        bf16 h = __float2bfloat16(v);
        bf16 l = __float2bfloat16(v - __bfloat162float(h));
        outH[(size_t)(y1 + i) * R + xo] = h;
        outL[(size_t)(y1 + i) * R + xo] = l;
    }
}

// ================= layernorm (writes hi/lo bf16) =================
__global__ void __launch_bounds__(256) ln_kernel(const float* __restrict__ in,
                                                 const float* __restrict__ gamma,
                                                 const float* __restrict__ beta,
                                                 bf16* __restrict__ outH,
                                                 bf16* __restrict__ outL)
{
    int row = blockIdx.x;
    const float* x = in + (size_t)row * D_MODEL;
    int t = threadIdx.x;
    float v[4];
    float s = 0.f;
#pragma unroll
    for (int i = 0; i < 4; i++) { v[i] = x[i*256 + t]; s += v[i]; }

    __shared__ float red[8];
    __shared__ float bcast;
#pragma unroll
    for (int o = 16; o > 0; o >>= 1) s += __shfl_xor_sync(0xffffffffu, s, o);
    if ((t & 31) == 0) red[t >> 5] = s;
    __syncthreads();
    if (t < 32) {
        float r = (t < 8) ? red[t] : 0.f;
#pragma unroll
        for (int o = 4; o > 0; o >>= 1) r += __shfl_xor_sync(0xffffffffu, r, o);
        if (t == 0) bcast = r;
    }
    __syncthreads();
    float mean = bcast * (1.f / D_MODEL);

    float s2 = 0.f;
#pragma unroll
    for (int i = 0; i < 4; i++) { float d = v[i] - mean; s2 += d*d; }
#pragma unroll
    for (int o = 16; o > 0; o >>= 1) s2 += __shfl_xor_sync(0xffffffffu, s2, o);
    __syncthreads();
    if ((t & 31) == 0) red[t >> 5] = s2;
    __syncthreads();
    if (t < 32) {
        float r = (t < 8) ? red[t] : 0.f;
#pragma unroll
        for (int o = 4; o > 0; o >>= 1) r += __shfl_xor_sync(0xffffffffu, r, o);
        if (t == 0) bcast = r;
    }
    __syncthreads();
    float rstd = rsqrtf(bcast * (1.f / D_MODEL) + 1e-5f);

#pragma unroll
    for (int i = 0; i < 4; i++) {
        int d = i*256 + t;
        float y = gamma[d] * (v[i] - mean) * rstd + beta[d];
        bf16 h = __float2bfloat16(y);
        outH[(size_t)row * D_MODEL + d] = h;
        outL[(size_t)row * D_MODEL + d] = __float2bfloat16(y - __bfloat162float(h));
    }
}

// ================= split-bf16 mma GEMM with cp.async pipeline =================
// C = A @ Bt^T, A given as (Ah,Al) bf16 [M,K], Bt as (Bh,Bl) bf16 [N,K].
// EPI: 0 = plain fp32; 1 = bias+res fp32; 2 = bias+gelu -> (Ch,Cl) bf16
#define ROW_BYTES  80
#define MAT_BYTES  (128*ROW_BYTES)      // 10240
#define STAGE_BYTES (4*MAT_BYTES)       // 40960
#define GEMM_SMEM  (2*STAGE_BYTES)      // 81920

template<int EPI>
__global__ void __launch_bounds__(256) gemm_bf(
    const bf16* __restrict__ Ah, const bf16* __restrict__ Al,
    const bf16* __restrict__ Bh, const bf16* __restrict__ Bl,
    const float* __restrict__ bias, const float* __restrict__ res,
    float* __restrict__ C, bf16* __restrict__ Ch, bf16* __restrict__ Cl,
    int M, int N, int K)
{
    extern __shared__ char dynsm[];
    uint32_t sbase = smem_u32(dynsm);

    int t = threadIdx.x;
    int lane = t & 31, wid = t >> 5;
    int warp_m = wid & 3;
    int warp_n = wid >> 2;
    int m0 = blockIdx.y * 128, n0 = blockIdx.x * 128;
    const int NC = K >> 5;

    const bf16* srcs[4] = { Ah + (size_t)m0 * K, Al + (size_t)m0 * K,
                            Bh + (size_t)n0 * K, Bl + (size_t)n0 * K };
    int crow = t >> 2;     // 0..63
    int cq   = t & 3;      // 16B quarter of the 64B chunk-row

    auto issue_copy = [&](int st, int k0) {
#pragma unroll
        for (int m = 0; m < 4; m++) {
            const bf16* s = srcs[m];
#pragma unroll
            for (int i = 0; i < 2; i++) {
                int row = crow + i * 64;
                uint32_t dst = sbase + (uint32_t)(st * STAGE_BYTES + m * MAT_BYTES
                                                  + row * ROW_BYTES + cq * 16);
                cp16(dst, s + (size_t)row * K + k0 + cq * 8);
            }
        }
        asm volatile("cp.async.commit_group;");
    };

    float acc[2][8][4];
#pragma unroll
    for (int mt = 0; mt < 2; mt++)
#pragma unroll
        for (int nt = 0; nt < 8; nt++)
#pragma unroll
            for (int r = 0; r < 4; r++) acc[mt][nt][r] = 0.f;

    auto compute_stage = [&](int st) {
        uint32_t stb = sbase + (uint32_t)st * STAGE_BYTES;
        uint32_t ah_base = stb;
        uint32_t bh_base = stb + 2*MAT_BYTES;
#pragma unroll
        for (int ks = 0; ks < 2; ks++) {
            uint32_t afh[2][4], afl[2][4];
#pragma unroll
            for (int mt = 0; mt < 2; mt++) {
                int row = warp_m * 32 + mt * 16 + (lane & 15);
                int kcol = ks * 16 + (lane >> 4) * 8;
                uint32_t addr = ah_base + (uint32_t)(row * ROW_BYTES + kcol * 2);
                LDSM_X4(afh[mt][0], afh[mt][1], afh[mt][2], afh[mt][3], addr);
                LDSM_X4(afl[mt][0], afl[mt][1], afl[mt][2], afl[mt][3], addr + MAT_BYTES);
            }
#pragma unroll
            for (int np = 0; np < 4; np++) {
                int nrow = warp_n * 64 + np * 16 + (lane & 7) + ((lane >> 4) << 3);
                int kcol = ks * 16 + ((lane >> 3) & 1) * 8;
                uint32_t addr = bh_base + (uint32_t)(nrow * ROW_BYTES + kcol * 2);
                uint32_t bfh[4], bfl[4];
                LDSM_X4(bfh[0], bfh[1], bfh[2], bfh[3], addr);
                LDSM_X4(bfl[0], bfl[1], bfl[2], bfl[3], addr + MAT_BYTES);
#pragma unroll
                for (int mt = 0; mt < 2; mt++) {
                    int nt0 = np * 2;
                    MMA_BF16(acc[mt][nt0],   afh[mt], bfh[0], bfh[1]);
                    MMA_BF16(acc[mt][nt0+1], afh[mt], bfh[2], bfh[3]);
                    MMA_BF16(acc[mt][nt0],   afh[mt], bfl[0], bfl[1]);
                    MMA_BF16(acc[mt][nt0+1], afh[mt], bfl[2], bfl[3]);
                    MMA_BF16(acc[mt][nt0],   afl[mt], bfh[0], bfh[1]);
                    MMA_BF16(acc[mt][nt0+1], afl[mt], bfh[2], bfh[3]);
                }
            }
        }
    };

    issue_copy(0, 0);

    for (int c = 0; c < NC; c++) {
        if (c + 1 < NC) {
            issue_copy((c + 1) & 1, (c + 1) * 32);
            asm volatile("cp.async.wait_group 1;");
        } else {
            asm volatile("cp.async.wait_group 0;");
        }
        __syncthreads();
        compute_stage(c & 1);
        __syncthreads();
    }

    int g   = lane >> 2;
    int tig = lane & 3;
#pragma unroll
    for (int mt = 0; mt < 2; mt++) {
#pragma unroll
        for (int nt = 0; nt < 8; nt++) {
            int col = n0 + warp_n * 64 + nt * 8 + 2 * tig;
            int row0 = m0 + warp_m * 32 + mt * 16 + g;
            int row1 = row0 + 8;
            float v00 = acc[mt][nt][0], v01 = acc[mt][nt][1];
            float v10 = acc[mt][nt][2], v11 = acc[mt][nt][3];
            if (EPI != 0) {
                float b0 = bias[col], b1 = bias[col + 1];
                v00 += b0; v01 += b1; v10 += b0; v11 += b1;
            }
            if (EPI == 2) {
                float vv[4] = {v00, v01, v10, v11};
#pragma unroll
                for (int q = 0; q < 4; q++) {
                    float xx = vv[q];
                    float u = 0.7978845608028654f * (xx + 0.044715f * xx * xx * xx);
                    vv[q] = 0.5f * xx * (1.f + tanhf(u));
                }
                v00 = vv[0]; v01 = vv[1]; v10 = vv[2]; v11 = vv[3];
                *(uint32_t*)(Ch + (size_t)row0 * N + col) = pack_hi(v00, v01);
                *(uint32_t*)(Cl + (size_t)row0 * N + col) = pack_lo(v00, v01);
                *(uint32_t*)(Ch + (size_t)row1 * N + col) = pack_hi(v10, v11);
                *(uint32_t*)(Cl + (size_t)row1 * N + col) = pack_lo(v10, v11);
            } else {
                if (EPI == 1) {
                    float2 r0 = *(const float2*)(res + (size_t)row0 * N + col);
                    float2 r1 = *(const float2*)(res + (size_t)row1 * N + col);
                    v00 += r0.x; v01 += r0.y; v10 += r1.x; v11 += r1.y;
                }
                *(float2*)(C + (size_t)row0 * N + col) = make_float2(v00, v01);
                *(float2*)(C + (size_t)row1 * N + col) = make_float2(v10, v11);
            }
        }
    }
}

// ================= tensor-core flash attention (split-bf16) =================
#define AST 144
#define AQ_MAT (128*AST)
#define AK_MAT (64*AST)
#define ATT_SMEM (2*AQ_MAT + 4*AK_MAT)   // 73728

__global__ void __launch_bounds__(256) attn_mma(
    const float* __restrict__ QKV, bf16* __restrict__ OH, bf16* __restrict__ OL)
{
    extern __shared__ char asmem[];
    uint32_t sb = smem_u32(asmem);
    const uint32_t QH = sb, QL = sb + AQ_MAT;
    const uint32_t KH = QL + AQ_MAT, KL = KH + AK_MAT;
    const uint32_t VH = KL + AK_MAT, VL = VH + AK_MAT;

    int t = threadIdx.x, lane = t & 31, wid = t >> 5;
    int qt = blockIdx.x, bh = blockIdx.y;
    int b = bh >> 4, h = bh & 15;
    int q0 = qt * 128;

    const float* base = QKV + (size_t)b * SEQ * QKV_W + h * HDIM;
    const float* Qg = base;
    const float* Kg = base + D_MODEL;
    const float* Vg = base + 2 * D_MODEL;

    for (int idx = t; idx < 2048; idx += 256) {
        int r = idx >> 4, c4 = (idx & 15) * 4;
        float4 v = *(const float4*)(Qg + (size_t)(q0 + r) * QKV_W + c4);
        uint32_t ad = QH + (uint32_t)(r * AST + c4 * 2);
        asm volatile("st.shared.v2.b32 [%0], {%1, %2};" :: "r"(ad),
                     "r"(pack_hi(v.x, v.y)), "r"(pack_hi(v.z, v.w)) : "memory");
        asm volatile("st.shared.v2.b32 [%0], {%1, %2};" :: "r"(ad + AQ_MAT),
                     "r"(pack_lo(v.x, v.y)), "r"(pack_lo(v.z, v.w)) : "memory");
    }
    __syncthreads();

    uint32_t qfh[4][4], qfl[4][4];
#pragma unroll
    for (int ks = 0; ks < 4; ks++) {
        int row = wid * 16 + (lane & 15);
        int kcol = ks * 16 + (lane >> 4) * 8;
        uint32_t ad = QH + (uint32_t)(row * AST + kcol * 2);
        LDSM_X4(qfh[ks][0], qfh[ks][1], qfh[ks][2], qfh[ks][3], ad);
        LDSM_X4(qfl[ks][0], qfl[ks][1], qfl[ks][2], qfl[ks][3], ad + AQ_MAT);
    }

    float oacc[8][4];
#pragma unroll
    for (int nt = 0; nt < 8; nt++)
#pragma unroll
        for (int e = 0; e < 4; e++) oacc[nt][e] = 0.f;
    float mrow[2] = {-1e30f, -1e30f};
    float lrow[2] = {0.f, 0.f};

    int qmax = q0 + wid * 16 + 15;
    int NK = qt * 2 + 2;
    int qrow0 = q0 + wid * 16 + (lane >> 2);
    int lj = 2 * (lane & 3);

    for (int kt = 0; kt < NK; kt++) {
        __syncthreads();
        for (int idx = t; idx < 1024; idx += 256) {
            int r = idx >> 4, c4 = (idx & 15) * 4;
            size_t grow = (size_t)(kt * 64 + r) * QKV_W + c4;
            uint32_t ad = (uint32_t)(r * AST + c4 * 2);
            float4 kv = *(const float4*)(Kg + grow);
            asm volatile("st.shared.v2.b32 [%0], {%1, %2};" :: "r"(KH + ad),
                         "r"(pack_hi(kv.x, kv.y)), "r"(pack_hi(kv.z, kv.w)) : "memory");
            asm volatile("st.shared.v2.b32 [%0], {%1, %2};" :: "r"(KL + ad),
                         "r"(pack_lo(kv.x, kv.y)), "r"(pack_lo(kv.z, kv.w)) : "memory");
            float4 vv = *(const float4*)(Vg + grow);
            asm volatile("st.shared.v2.b32 [%0], {%1, %2};" :: "r"(VH + ad),
                         "r"(pack_hi(vv.x, vv.y)), "r"(pack_hi(vv.z, vv.w)) : "memory");
            asm volatile("st.shared.v2.b32 [%0], {%1, %2};" :: "r"(VL + ad),
                         "r"(pack_lo(vv.x, vv.y)), "r"(pack_lo(vv.z, vv.w)) : "memory");
        }
        __syncthreads();
        if (kt * 64 > qmax) continue;

        float sacc[8][4];
#pragma unroll
        for (int nt = 0; nt < 8; nt++)
#pragma unroll
            for (int e = 0; e < 4; e++) sacc[nt][e] = 0.f;
#pragma unroll
        for (int ks = 0; ks < 4; ks++) {
#pragma unroll
            for (int np = 0; np < 4; np++) {
                int nrow = np * 16 + (lane & 7) + ((lane >> 4) << 3);
                int kcol = ks * 16 + ((lane >> 3) & 1) * 8;
                uint32_t ad = KH + (uint32_t)(nrow * AST + kcol * 2);
                uint32_t bfh[4], bfl[4];
                LDSM_X4(bfh[0], bfh[1], bfh[2], bfh[3], ad);
                LDSM_X4(bfl[0], bfl[1], bfl[2], bfl[3], ad + AK_MAT);
                int nt0 = np * 2;
                MMA_BF16(sacc[nt0],   qfh[ks], bfh[0], bfh[1]);
                MMA_BF16(sacc[nt0+1], qfh[ks], bfh[2], bfh[3]);
                MMA_BF16(sacc[nt0],   qfh[ks], bfl[0], bfl[1]);
                MMA_BF16(sacc[nt0+1], qfh[ks], bfl[2], bfl[3]);
                MMA_BF16(sacc[nt0],   qfl[ks], bfh[0], bfh[1]);
                MMA_BF16(sacc[nt0+1], qfl[ks], bfh[2], bfh[3]);
            }
        }

        bool maskt = (kt >= NK - 2);
#pragma unroll
        for (int nt = 0; nt < 8; nt++) {
            int kgb = kt * 64 + nt * 8 + lj;
#pragma unroll
            for (int e = 0; e < 4; e++) {
                float s = sacc[nt][e] * 0.125f;
                if (maskt) {
                    int kg = kgb + (e & 1);
                    int qg = qrow0 + (e >> 1) * 8;
                    if (kg > qg) s = -1e30f;
                }
                sacc[nt][e] = s;
            }
        }

        float tm0 = -1e30f, tm1 = -1e30f;
#pragma unroll
        for (int nt = 0; nt < 8; nt++) {
            tm0 = fmaxf(tm0, fmaxf(sacc[nt][0], sacc[nt][1]));
            tm1 = fmaxf(tm1, fmaxf(sacc[nt][2], sacc[nt][3]));
        }
        tm0 = fmaxf(tm0, __shfl_xor_sync(0xffffffffu, tm0, 1));
        tm0 = fmaxf(tm0, __shfl_xor_sync(0xffffffffu, tm0, 2));
        tm1 = fmaxf(tm1, __shfl_xor_sync(0xffffffffu, tm1, 1));
        tm1 = fmaxf(tm1, __shfl_xor_sync(0xffffffffu, tm1, 2));
        float mn0 = fmaxf(mrow[0], tm0), mn1 = fmaxf(mrow[1], tm1);
        float al0 = __expf(mrow[0] - mn0), al1 = __expf(mrow[1] - mn1);
        mrow[0] = mn0; mrow[1] = mn1;

        float rs0 = 0.f, rs1 = 0.f;
#pragma unroll
        for (int nt = 0; nt < 8; nt++) {
            float p0 = __expf(sacc[nt][0] - mn0);
            float p1 = __expf(sacc[nt][1] - mn0);
            float p2 = __expf(sacc[nt][2] - mn1);
            float p3 = __expf(sacc[nt][3] - mn1);
            sacc[nt][0] = p0; sacc[nt][1] = p1; sacc[nt][2] = p2; sacc[nt][3] = p3;
            rs0 += p0 + p1; rs1 += p2 + p3;
        }
        rs0 += __shfl_xor_sync(0xffffffffu, rs0, 1);
        rs0 += __shfl_xor_sync(0xffffffffu, rs0, 2);
        rs1 += __shfl_xor_sync(0xffffffffu, rs1, 1);
        rs1 += __shfl_xor_sync(0xffffffffu, rs1, 2);
        lrow[0] = lrow[0] * al0 + rs0;
        lrow[1] = lrow[1] * al1 + rs1;
#pragma unroll
        for (int nt = 0; nt < 8; nt++) {
            oacc[nt][0] *= al0; oacc[nt][1] *= al0;
            oacc[nt][2] *= al1; oacc[nt][3] *= al1;
        }

#pragma unroll
        for (int kt2 = 0; kt2 < 4; kt2++) {
            uint32_t aPh[4], aPl[4];
            int n0i = 2 * kt2, n1i = 2 * kt2 + 1;
            aPh[0] = pack_hi(sacc[n0i][0], sacc[n0i][1]);
            aPh[1] = pack_hi(sacc[n0i][2], sacc[n0i][3]);
            aPh[2] = pack_hi(sacc[n1i][0], sacc[n1i][1]);
            aPh[3] = pack_hi(sacc[n1i][2], sacc[n1i][3]);
            aPl[0] = pack_lo(sacc[n0i][0], sacc[n0i][1]);
            aPl[1] = pack_lo(sacc[n0i][2], sacc[n0i][3]);
            aPl[2] = pack_lo(sacc[n1i][0], sacc[n1i][1]);
            aPl[3] = pack_lo(sacc[n1i][2], sacc[n1i][3]);
#pragma unroll
            for (int dp = 0; dp < 4; dp++) {
                int krow = kt2 * 16 + ((lane >> 3) & 1) * 8 + (lane & 7);
                int dbyte = dp * 32 + (lane >> 4) * 16;
                uint32_t ad = VH + (uint32_t)(krow * AST + dbyte);
                uint32_t vfh[4], vfl[4];
                LDSM_X4_T(vfh[0], vfh[1], vfh[2], vfh[3], ad);
                LDSM_X4_T(vfl[0], vfl[1], vfl[2], vfl[3], ad + AK_MAT);
                MMA_BF16(oacc[2*dp],   aPh, vfh[0], vfh[1]);
                MMA_BF16(oacc[2*dp+1], aPh, vfh[2], vfh[3]);
                MMA_BF16(oacc[2*dp],   aPh, vfl[0], vfl[1]);
                MMA_BF16(oacc[2*dp+1], aPh, vfl[2], vfl[3]);
                MMA_BF16(oacc[2*dp],   aPl, vfh[0], vfh[1]);
                MMA_BF16(oacc[2*dp+1], aPl, vfh[2], vfh[3]);
            }
        }
    }

    float inv0 = 1.f / lrow[0], inv1 = 1.f / lrow[1];
    size_t ob = ((size_t)b * SEQ + qrow0) * D_MODEL + h * HDIM;
#pragma unroll
    for (int nt = 0; nt < 8; nt++) {
        int cb = nt * 8 + lj;
        float a0 = oacc[nt][0] * inv0, a1 = oacc[nt][1] * inv0;
        float a2 = oacc[nt][2] * inv1, a3 = oacc[nt][3] * inv1;
        *(uint32_t*)(OH + ob + cb) = pack_hi(a0, a1);
        *(uint32_t*)(OL + ob + cb) = pack_lo(a0, a1);
        *(uint32_t*)(OH + ob + 8 * D_MODEL + cb) = pack_hi(a2, a3);
        *(uint32_t*)(OL + ob + 8 * D_MODEL + cb) = pack_lo(a2, a3);
    }
}

// ================= launch =================
extern "C" void kernel_launch(void* const* d_in, const int* in_sizes, int n_in,
                              void* d_out, int out_size)
{
    (void)in_sizes; (void)n_in; (void)out_size;
    const float* x  = (const float*)d_in[0];
    const float* Wq = (const float*)d_in[1];
    const float* Wk = (const float*)d_in[2];
    const float* Wv = (const float*)d_in[3];
    const float* Wo = (const float*)d_in[4];
    const float* bo = (const float*)d_in[5];
    const float* W1 = (const float*)d_in[6];
    const float* b1 = (const float*)d_in[7];
    const float* W2 = (const float*)d_in[8];
    const float* b2 = (const float*)d_in[9];
    const float* g1 = (const float*)d_in[10];
    const float* s1 = (const float*)d_in[11];
    const float* g2 = (const float*)d_in[12];
    const float* s2 = (const float*)d_in[13];
    float* out = (float*)d_out;

    bf16 *lnH, *lnL, *ctxH, *ctxL, *f1H, *f1L;
    bf16 *wqkvTH, *wqkvTL, *woTH, *woTL, *w1TH, *w1TL, *w2TH, *w2TL;
    float *qkv, *h;
    cudaGetSymbolAddress((void**)&lnH,    g_lnH);
    cudaGetSymbolAddress((void**)&lnL,    g_lnL);
    cudaGetSymbolAddress((void**)&qkv,    g_qkv);
    cudaGetSymbolAddress((void**)&ctxH,   g_ctxH);
    cudaGetSymbolAddress((void**)&ctxL,   g_ctxL);
    cudaGetSymbolAddress((void**)&h,      g_h);
    cudaGetSymbolAddress((void**)&f1H,    g_f1H);
    cudaGetSymbolAddress((void**)&f1L,    g_f1L);
    cudaGetSymbolAddress((void**)&wqkvTH, g_wqkvTH);
    cudaGetSymbolAddress((void**)&wqkvTL, g_wqkvTL);
    cudaGetSymbolAddress((void**)&woTH,   g_woTH);
    cudaGetSymbolAddress((void**)&woTL,   g_woTL);
    cudaGetSymbolAddress((void**)&w1TH,   g_w1TH);
    cudaGetSymbolAddress((void**)&w1TL,   g_w1TL);
    cudaGetSymbolAddress((void**)&w2TH,   g_w2TH);
    cudaGetSymbolAddress((void**)&w2TL,   g_w2TL);

    cudaFuncSetAttribute(gemm_bf<0>, cudaFuncAttributeMaxDynamicSharedMemorySize, GEMM_SMEM);
    cudaFuncSetAttribute(gemm_bf<1>, cudaFuncAttributeMaxDynamicSharedMemorySize, GEMM_SMEM);
    cudaFuncSetAttribute(gemm_bf<2>, cudaFuncAttributeMaxDynamicSharedMemorySize, GEMM_SMEM);
    cudaFuncSetAttribute(attn_mma, cudaFuncAttributeMaxDynamicSharedMemorySize, ATT_SMEM);

    dim3 tb(32, 8);
    transpose_split_kernel<<<dim3(D_MODEL/32, D_MODEL/32), tb>>>(Wq, wqkvTH, wqkvTL, D_MODEL, D_MODEL);
    transpose_split_kernel<<<dim3(D_MODEL/32, D_MODEL/32), tb>>>(Wk, wqkvTH + 1024*(size_t)D_MODEL, wqkvTL + 1024*(size_t)D_MODEL, D_MODEL, D_MODEL);
    transpose_split_kernel<<<dim3(D_MODEL/32, D_MODEL/32), tb>>>(Wv, wqkvTH + 2048*(size_t)D_MODEL, wqkvTL + 2048*(size_t)D_MODEL, D_MODEL, D_MODEL);
    transpose_split_kernel<<<dim3(D_MODEL/32, D_MODEL/32), tb>>>(Wo, woTH, woTL, D_MODEL, D_MODEL);
    transpose_split_kernel<<<dim3(DFF/32,     D_MODEL/32), tb>>>(W1, w1TH, w1TL, D_MODEL, DFF);
    transpose_split_kernel<<<dim3(D_MODEL/32, DFF/32),     tb>>>(W2, w2TH, w2TL, DFF, D_MODEL);

    // 1. ln1 = LN(x) -> hi/lo
    ln_kernel<<<NTOK, 256>>>(x, g1, s1, lnH, lnL);
    // 2. qkv = ln1 @ [Wq|Wk|Wv]   (fp32 out)
    gemm_bf<0><<<dim3(QKV_W/128, NTOK/128), 256, GEMM_SMEM>>>(
        lnH, lnL, wqkvTH, wqkvTL, nullptr, nullptr, qkv, nullptr, nullptr, NTOK, QKV_W, D_MODEL);
    // 3. causal attention -> ctx hi/lo
    attn_mma<<<dim3(SEQ/128, BATCH*NHEADS), 256, ATT_SMEM>>>(qkv, ctxH, ctxL);
    // 4. h = x + ctx @ Wo + bo
    gemm_bf<1><<<dim3(D_MODEL/128, NTOK/128), 256, GEMM_SMEM>>>(
        ctxH, ctxL, woTH, woTL, bo, x, h, nullptr, nullptr, NTOK, D_MODEL, D_MODEL);
    // 5. ln2 = LN(h) -> hi/lo
    ln_kernel<<<NTOK, 256>>>(h, g2, s2, lnH, lnL);
    // 6. f1 = gelu(ln2 @ W1 + b1) -> hi/lo
    gemm_bf<2><<<dim3(DFF/128, NTOK/128), 256, GEMM_SMEM>>>(
        lnH, lnL, w1TH, w1TL, b1, nullptr, nullptr, f1H, f1L, NTOK, DFF, D_MODEL);
    // 7. out = h + f1 @ W2 + b2
    gemm_bf<1><<<dim3(D_MODEL/128, NTOK/128), 256, GEMM_SMEM>>>(
        f1H, f1L, w2TH, w2TL, b2, h, out, nullptr, nullptr, NTOK, D_MODEL, DFF);
}

// round 7
// speedup vs baseline: 1.2697x; 1.2697x over previous
#include <cuda_runtime.h>
#include <cuda_bf16.h>
#include <cuda_fp16.h>
#include <cstdint>
#include <math.h>

#define D_MODEL 1024
#define DFF     4096
#define SEQ     2048
#define BATCH   2
#define NTOK    (SEQ*BATCH)      // 4096
#define NHEADS  16
#define HDIM    64
#define QKV_W   3072

typedef __nv_bfloat16 bf16;

// ---------------- scratch ----------------
__device__ float g_ln  [NTOK*(size_t)D_MODEL];
__device__ float g_qkv [NTOK*(size_t)QKV_W];
__device__ float g_ctx [NTOK*(size_t)D_MODEL];
__device__ float g_h   [NTOK*(size_t)D_MODEL];
__device__ float g_f1  [NTOK*(size_t)DFF];
__device__ float g_wqkvT[(size_t)QKV_W*D_MODEL];
__device__ float g_woT  [(size_t)D_MODEL*D_MODEL];
__device__ __half g_w1TH[(size_t)DFF*D_MODEL];
__device__ __half g_w1TL[(size_t)DFF*D_MODEL];
__device__ __half g_w2TH[(size_t)D_MODEL*DFF];
__device__ __half g_w2TL[(size_t)D_MODEL*DFF];

// ================= helpers =================
__device__ __forceinline__ uint32_t smem_u32(const void* p) {
    uint32_t a;
    asm("{ .reg .u64 t; cvta.to.shared.u64 t, %1; cvt.u32.u64 %0, t; }" : "=r"(a) : "l"(p));
    return a;
}

#define LDSM_X4(r0,r1,r2,r3,a) \
    asm volatile("ldmatrix.sync.aligned.m8n8.x4.shared.b16 {%0,%1,%2,%3}, [%4];" \
        : "=r"(r0), "=r"(r1), "=r"(r2), "=r"(r3) : "r"(a))
#define LDSM_X4_T(r0,r1,r2,r3,a) \
    asm volatile("ldmatrix.sync.aligned.m8n8.x4.trans.shared.b16 {%0,%1,%2,%3}, [%4];" \
        : "=r"(r0), "=r"(r1), "=r"(r2), "=r"(r3) : "r"(a))

#define MMA_BF16(c, a, b0, b1) \
    asm volatile("mma.sync.aligned.m16n8k16.row.col.f32.bf16.bf16.f32 " \
        "{%0,%1,%2,%3}, {%4,%5,%6,%7}, {%8,%9}, {%0,%1,%2,%3};" \
        : "+f"((c)[0]), "+f"((c)[1]), "+f"((c)[2]), "+f"((c)[3]) \
        : "r"((a)[0]), "r"((a)[1]), "r"((a)[2]), "r"((a)[3]), "r"(b0), "r"(b1))

#define MMA_F16(c, a, b0, b1) \
    asm volatile("mma.sync.aligned.m16n8k16.row.col.f32.f16.f16.f32 " \
        "{%0,%1,%2,%3}, {%4,%5,%6,%7}, {%8,%9}, {%0,%1,%2,%3};" \
        : "+f"((c)[0]), "+f"((c)[1]), "+f"((c)[2]), "+f"((c)[3]) \
        : "r"((a)[0]), "r"((a)[1]), "r"((a)[2]), "r"((a)[3]), "r"(b0), "r"(b1))

__device__ __forceinline__ uint32_t pack_bf2(bf16 a, bf16 b) {
    __nv_bfloat162 t; t.x = a; t.y = b;
    return *(uint32_t*)&t;
}
__device__ __forceinline__ uint32_t pack_hi(float a, float b) {
    return pack_bf2(__float2bfloat16(a), __float2bfloat16(b));
}
__device__ __forceinline__ uint32_t pack_lo(float a, float b) {
    bf16 ha = __float2bfloat16(a), hb = __float2bfloat16(b);
    return pack_bf2(__float2bfloat16(a - __bfloat162float(ha)),
                    __float2bfloat16(b - __bfloat162float(hb)));
}
__device__ __forceinline__ uint32_t pack_h2(float a, float b) {
    __half2 t; t.x = __float2half_rn(a); t.y = __float2half_rn(b);
    return *(uint32_t*)&t;
}
__device__ __forceinline__ void cp16(uint32_t dst, const void* src) {
    asm volatile("cp.async.cg.shared.global [%0], [%1], 16;" :: "r"(dst), "l"(src));
}

// ================= weight transposes =================
__global__ void __launch_bounds__(256) transpose_kernel(const float* __restrict__ in,
                                                        float* __restrict__ out, int R, int C)
{
    __shared__ float tile[32][33];
    int tx = threadIdx.x, ty = threadIdx.y;
    int x = blockIdx.x * 32 + tx;
    int y0 = blockIdx.y * 32;
#pragma unroll
    for (int i = ty; i < 32; i += 8)
        tile[i][tx] = in[(size_t)(y0 + i) * C + x];
    __syncthreads();
    int xo = y0 + tx;
    int y1 = blockIdx.x * 32;
#pragma unroll
    for (int i = ty; i < 32; i += 8)
        out[(size_t)(y1 + i) * R + xo] = tile[tx][i];
}

__global__ void __launch_bounds__(256) transpose_split_h(
    const float* __restrict__ in, __half* __restrict__ outH, __half* __restrict__ outL,
    int R, int C)
{
    __shared__ float tile[32][33];
    int tx = threadIdx.x, ty = threadIdx.y;
    int x = blockIdx.x * 32 + tx;
    int y0 = blockIdx.y * 32;
#pragma unroll
    for (int i = ty; i < 32; i += 8)
        tile[i][tx] = in[(size_t)(y0 + i) * C + x];
    __syncthreads();
    int xo = y0 + tx;
    int y1 = blockIdx.x * 32;
#pragma unroll
    for (int i = ty; i < 32; i += 8) {
        float v = tile[tx][i];
        __half h = __float2half_rn(v);
        outH[(size_t)(y1 + i) * R + xo] = h;
        outL[(size_t)(y1 + i) * R + xo] = __float2half_rn(v - __half2float(h));
    }
}

// ================= layernorm =================
__global__ void __launch_bounds__(256) ln_kernel(const float* __restrict__ in,
                                                 const float* __restrict__ gamma,
                                                 const float* __restrict__ beta,
                                                 float* __restrict__ out)
{
    int row = blockIdx.x;
    const float* x = in + (size_t)row * D_MODEL;
    int t = threadIdx.x;
    float v[4];
    float s = 0.f;
#pragma unroll
    for (int i = 0; i < 4; i++) { v[i] = x[i*256 + t]; s += v[i]; }

    __shared__ float red[8];
    __shared__ float bcast;
#pragma unroll
    for (int o = 16; o > 0; o >>= 1) s += __shfl_xor_sync(0xffffffffu, s, o);
    if ((t & 31) == 0) red[t >> 5] = s;
    __syncthreads();
    if (t < 32) {
        float r = (t < 8) ? red[t] : 0.f;
#pragma unroll
        for (int o = 4; o > 0; o >>= 1) r += __shfl_xor_sync(0xffffffffu, r, o);
        if (t == 0) bcast = r;
    }
    __syncthreads();
    float mean = bcast * (1.f / D_MODEL);

    float s2 = 0.f;
#pragma unroll
    for (int i = 0; i < 4; i++) { float d = v[i] - mean; s2 += d*d; }
#pragma unroll
    for (int o = 16; o > 0; o >>= 1) s2 += __shfl_xor_sync(0xffffffffu, s2, o);
    __syncthreads();
    if ((t & 31) == 0) red[t >> 5] = s2;
    __syncthreads();
    if (t < 32) {
        float r = (t < 8) ? red[t] : 0.f;
#pragma unroll
        for (int o = 4; o > 0; o >>= 1) r += __shfl_xor_sync(0xffffffffu, r, o);
        if (t == 0) bcast = r;
    }
    __syncthreads();
    float rstd = rsqrtf(bcast * (1.f / D_MODEL) + 1e-5f);

#pragma unroll
    for (int i = 0; i < 4; i++) {
        int d = i*256 + t;
        out[(size_t)row * D_MODEL + d] = gamma[d] * (v[i] - mean) * rstd + beta[d];
    }
}

// ================= GEMM common epilogue =================
template<int EPI>
__device__ __forceinline__ void gemm_epilogue(
    float acc[2][8][4], const float* bias, const float* res, float* C,
    int m0, int n0, int warp_m, int warp_n, int lane, int N)
{
    int g   = lane >> 2;
    int tig = lane & 3;
#pragma unroll
    for (int mt = 0; mt < 2; mt++) {
#pragma unroll
        for (int nt = 0; nt < 8; nt++) {
            int col = n0 + warp_n * 64 + nt * 8 + 2 * tig;
            int row0 = m0 + warp_m * 32 + mt * 16 + g;
            int row1 = row0 + 8;
            float v00 = acc[mt][nt][0], v01 = acc[mt][nt][1];
            float v10 = acc[mt][nt][2], v11 = acc[mt][nt][3];
            if (EPI != 0) {
                float b0 = bias[col], b1 = bias[col + 1];
                v00 += b0; v01 += b1; v10 += b0; v11 += b1;
            }
            if (EPI == 2) {
                float vv[4] = {v00, v01, v10, v11};
#pragma unroll
                for (int q = 0; q < 4; q++) {
                    float xx = vv[q];
                    float u = 0.7978845608028654f * (xx + 0.044715f * xx * xx * xx);
                    vv[q] = 0.5f * xx * (1.f + tanhf(u));
                }
                v00 = vv[0]; v01 = vv[1]; v10 = vv[2]; v11 = vv[3];
            }
            if (EPI == 1) {
                float2 r0 = *(const float2*)(res + (size_t)row0 * N + col);
                float2 r1 = *(const float2*)(res + (size_t)row1 * N + col);
                v00 += r0.x; v01 += r0.y; v10 += r1.x; v11 += r1.y;
            }
            *(float2*)(C + (size_t)row0 * N + col) = make_float2(v00, v01);
            *(float2*)(C + (size_t)row1 * N + col) = make_float2(v10, v11);
        }
    }
}

// ================= split-bf16 3-product GEMM (R5, proven) =================
#define ROW_BYTES  80
#define MAT_BYTES  (128*ROW_BYTES)
#define STAGE_BYTES (4*MAT_BYTES)
#define GEMM_SMEM  (2*STAGE_BYTES)      // 81920

template<int EPI>
__global__ void __launch_bounds__(256) gemm_mma(
    const float* __restrict__ A, const float* __restrict__ Bt,
    const float* __restrict__ bias, const float* __restrict__ res,
    float* __restrict__ C, int M, int N, int K)
{
    extern __shared__ char dynsm[];
    uint32_t sbase = smem_u32(dynsm);

    int t = threadIdx.x;
    int lane = t & 31, wid = t >> 5;
    int warp_m = wid & 3;
    int warp_n = wid >> 2;
    int m0 = blockIdx.y * 128, n0 = blockIdx.x * 128;
    const int NC = K >> 5;

    const float* Ap = A  + (size_t)m0 * K;
    const float* Bp = Bt + (size_t)n0 * K;

    int lrow  = t >> 3;
    int lcol4 = (t & 7) * 4;

    float acc[2][8][4];
#pragma unroll
    for (int mt = 0; mt < 2; mt++)
#pragma unroll
        for (int nt = 0; nt < 8; nt++)
#pragma unroll
            for (int r = 0; r < 4; r++) acc[mt][nt][r] = 0.f;

    auto sts_pair = [&](uint32_t mat_base, int row, int col4, float4 v) {
        uint32_t ah = mat_base + (uint32_t)(row * ROW_BYTES + col4 * 2);
        asm volatile("st.shared.v2.b32 [%0], {%1, %2};" :: "r"(ah),
                     "r"(pack_hi(v.x, v.y)), "r"(pack_hi(v.z, v.w)) : "memory");
        asm volatile("st.shared.v2.b32 [%0], {%1, %2};" :: "r"(ah + MAT_BYTES),
                     "r"(pack_lo(v.x, v.y)), "r"(pack_lo(v.z, v.w)) : "memory");
    };

    auto load_chunk_direct = [&](int k0, int st) {
        uint32_t stb = sbase + (uint32_t)st * STAGE_BYTES;
#pragma unroll
        for (int i = 0; i < 4; i++) {
            int row = lrow + i * 32;
            float4 a4 = *(const float4*)(Ap + (size_t)row * K + k0 + lcol4);
            sts_pair(stb, row, lcol4, a4);
            float4 b4 = *(const float4*)(Bp + (size_t)row * K + k0 + lcol4);
            sts_pair(stb + 2*MAT_BYTES, row, lcol4, b4);
        }
    };

    auto compute_stage = [&](int st) {
        uint32_t stb = sbase + (uint32_t)st * STAGE_BYTES;
        uint32_t ah_base = stb;
        uint32_t bh_base = stb + 2*MAT_BYTES;
#pragma unroll
        for (int ks = 0; ks < 2; ks++) {
            uint32_t afh[2][4], afl[2][4];
#pragma unroll
            for (int mt = 0; mt < 2; mt++) {
                int row = warp_m * 32 + mt * 16 + (lane & 15);
                int kcol = ks * 16 + (lane >> 4) * 8;
                uint32_t addr = ah_base + (uint32_t)(row * ROW_BYTES + kcol * 2);
                LDSM_X4(afh[mt][0], afh[mt][1], afh[mt][2], afh[mt][3], addr);
                LDSM_X4(afl[mt][0], afl[mt][1], afl[mt][2], afl[mt][3], addr + MAT_BYTES);
            }
#pragma unroll
            for (int np = 0; np < 4; np++) {
                int nrow = warp_n * 64 + np * 16 + (lane & 7) + ((lane >> 4) << 3);
                int kcol = ks * 16 + ((lane >> 3) & 1) * 8;
                uint32_t addr = bh_base + (uint32_t)(nrow * ROW_BYTES + kcol * 2);
                uint32_t bfh[4], bfl[4];
                LDSM_X4(bfh[0], bfh[1], bfh[2], bfh[3], addr);
                LDSM_X4(bfl[0], bfl[1], bfl[2], bfl[3], addr + MAT_BYTES);
#pragma unroll
                for (int mt = 0; mt < 2; mt++) {
                    int nt0 = np * 2;
                    MMA_BF16(acc[mt][nt0],   afh[mt], bfh[0], bfh[1]);
                    MMA_BF16(acc[mt][nt0+1], afh[mt], bfh[2], bfh[3]);
                    MMA_BF16(acc[mt][nt0],   afh[mt], bfl[0], bfl[1]);
                    MMA_BF16(acc[mt][nt0+1], afh[mt], bfl[2], bfl[3]);
                    MMA_BF16(acc[mt][nt0],   afl[mt], bfh[0], bfh[1]);
                    MMA_BF16(acc[mt][nt0+1], afl[mt], bfh[2], bfh[3]);
                }
            }
        }
    };

    load_chunk_direct(0, 0);
    __syncthreads();

    for (int c = 0; c < NC; c++) {
        int st = c & 1;
        bool has_next = (c + 1 < NC);
        float4 abuf[4], bbuf[4];
        if (has_next) {
            int k0 = (c + 1) * 32;
#pragma unroll
            for (int i = 0; i < 4; i++) {
                int row = lrow + i * 32;
                abuf[i] = *(const float4*)(Ap + (size_t)row * K + k0 + lcol4);
                bbuf[i] = *(const float4*)(Bp + (size_t)row * K + k0 + lcol4);
            }
        }
        compute_stage(st);
        if (has_next) {
            uint32_t stb = sbase + (uint32_t)(1 - st) * STAGE_BYTES;
#pragma unroll
            for (int i = 0; i < 4; i++) {
                int row = lrow + i * 32;
                sts_pair(stb, row, lcol4, abuf[i]);
                sts_pair(stb + 2*MAT_BYTES, row, lcol4, bbuf[i]);
            }
        }
        __syncthreads();
    }

    gemm_epilogue<EPI>(acc, bias, res, C, m0, n0, warp_m, warp_n, lane, N);
}

// ================= fp16 2-product FFN GEMM =================
// C = A(fp32,[M,K]) @ Bt^T with Bt pre-split fp16 (Bh,Bl)[N,K].
// smem stage: [Ah | Bh | Bl] each MAT_BYTES -> 30720/stage, 2 stages.
#define STAGE2_BYTES (3*MAT_BYTES)       // 30720
#define GEMM2_SMEM   (2*STAGE2_BYTES)    // 61440

template<int EPI>
__global__ void __launch_bounds__(256) gemm2(
    const float* __restrict__ A,
    const __half* __restrict__ Bh, const __half* __restrict__ Bl,
    const float* __restrict__ bias, const float* __restrict__ res,
    float* __restrict__ C, int M, int N, int K)
{
    extern __shared__ char dynsm[];
    uint32_t sbase = smem_u32(dynsm);

    int t = threadIdx.x;
    int lane = t & 31, wid = t >> 5;
    int warp_m = wid & 3;
    int warp_n = wid >> 2;
    int m0 = blockIdx.y * 128, n0 = blockIdx.x * 128;
    const int NC = K >> 5;

    const float* Ap = A + (size_t)m0 * K;
    const __half* Bsrc[2] = { Bh + (size_t)n0 * K, Bl + (size_t)n0 * K };

    int lrow  = t >> 3;        // A: 0..31 base row
    int lcol4 = (t & 7) * 4;
    int brow  = t >> 2;        // B: 0..63 base row
    int bq    = t & 3;         // 16B quarter of 64B row

    float acc[2][8][4];
#pragma unroll
    for (int mt = 0; mt < 2; mt++)
#pragma unroll
        for (int nt = 0; nt < 8; nt++)
#pragma unroll
            for (int r = 0; r < 4; r++) acc[mt][nt][r] = 0.f;

    auto issue_B = [&](int st, int k0) {
#pragma unroll
        for (int m = 0; m < 2; m++) {
#pragma unroll
            for (int i = 0; i < 2; i++) {
                int row = brow + i * 64;
                uint32_t dst = sbase + (uint32_t)(st * STAGE2_BYTES + (1 + m) * MAT_BYTES
                                                  + row * ROW_BYTES + bq * 16);
                cp16(dst, Bsrc[m] + (size_t)row * K + k0 + bq * 8);
            }
        }
        asm volatile("cp.async.commit_group;");
    };

    auto sts_A = [&](int st, int row, int col4, float4 v) {
        uint32_t ad = sbase + (uint32_t)(st * STAGE2_BYTES + row * ROW_BYTES + col4 * 2);
        asm volatile("st.shared.v2.b32 [%0], {%1, %2};" :: "r"(ad),
                     "r"(pack_h2(v.x, v.y)), "r"(pack_h2(v.z, v.w)) : "memory");
    };

    auto compute_stage = [&](int st) {
        uint32_t stb = sbase + (uint32_t)st * STAGE2_BYTES;
        uint32_t bh_base = stb + MAT_BYTES;
#pragma unroll
        for (int ks = 0; ks < 2; ks++) {
            uint32_t af[2][4];
#pragma unroll
            for (int mt = 0; mt < 2; mt++) {
                int row = warp_m * 32 + mt * 16 + (lane & 15);
                int kcol = ks * 16 + (lane >> 4) * 8;
                uint32_t addr = stb + (uint32_t)(row * ROW_BYTES + kcol * 2);
                LDSM_X4(af[mt][0], af[mt][1], af[mt][2], af[mt][3], addr);
            }
#pragma unroll
            for (int np = 0; np < 4; np++) {
                int nrow = warp_n * 64 + np * 16 + (lane & 7) + ((lane >> 4) << 3);
                int kcol = ks * 16 + ((lane >> 3) & 1) * 8;
                uint32_t addr = bh_base + (uint32_t)(nrow * ROW_BYTES + kcol * 2);
                uint32_t bfh[4], bfl[4];
                LDSM_X4(bfh[0], bfh[1], bfh[2], bfh[3], addr);
                LDSM_X4(bfl[0], bfl[1], bfl[2], bfl[3], addr + MAT_BYTES);
#pragma unroll
                for (int mt = 0; mt < 2; mt++) {
                    int nt0 = np * 2;
                    MMA_F16(acc[mt][nt0],   af[mt], bfh[0], bfh[1]);
                    MMA_F16(acc[mt][nt0+1], af[mt], bfh[2], bfh[3]);
                    MMA_F16(acc[mt][nt0],   af[mt], bfl[0], bfl[1]);
                    MMA_F16(acc[mt][nt0+1], af[mt], bfl[2], bfl[3]);
                }
            }
        }
    };

    // prologue: chunk 0
    issue_B(0, 0);
    {
#pragma unroll
        for (int i = 0; i < 4; i++) {
            int row = lrow + i * 32;
            float4 a4 = *(const float4*)(Ap + (size_t)row * K + lcol4);
            sts_A(0, row, lcol4, a4);
        }
    }
    asm volatile("cp.async.wait_group 0;");
    __syncthreads();

    for (int c = 0; c < NC; c++) {
        int st = c & 1;
        bool has_next = (c + 1 < NC);
        float4 abuf[4];
        if (has_next) {
            int k0 = (c + 1) * 32;
            issue_B(1 - st, k0);
#pragma unroll
            for (int i = 0; i < 4; i++) {
                int row = lrow + i * 32;
                abuf[i] = *(const float4*)(Ap + (size_t)row * K + k0 + lcol4);
            }
        }
        compute_stage(st);
        if (has_next) {
#pragma unroll
            for (int i = 0; i < 4; i++) {
                int row = lrow + i * 32;
                sts_A(1 - st, row, lcol4, abuf[i]);
            }
        }
        asm volatile("cp.async.wait_group 0;");
        __syncthreads();
    }

    gemm_epilogue<EPI>(acc, bias, res, C, m0, n0, warp_m, warp_n, lane, N);
}

// ================= tensor-core flash attention (R5, proven) =================
#define AST 144
#define AQ_MAT (128*AST)
#define AK_MAT (64*AST)
#define ATT_SMEM (2*AQ_MAT + 4*AK_MAT)

__global__ void __launch_bounds__(256) attn_mma(
    const float* __restrict__ QKV, float* __restrict__ O)
{
    extern __shared__ char asmem[];
    uint32_t sb = smem_u32(asmem);
    const uint32_t QH = sb, QL = sb + AQ_MAT;
    const uint32_t KH = QL + AQ_MAT, KL = KH + AK_MAT;
    const uint32_t VH = KL + AK_MAT, VL = VH + AK_MAT;

    int t = threadIdx.x, lane = t & 31, wid = t >> 5;
    int qt = blockIdx.x, bh = blockIdx.y;
    int b = bh >> 4, h = bh & 15;
    int q0 = qt * 128;

    const float* base = QKV + (size_t)b * SEQ * QKV_W + h * HDIM;
    const float* Qg = base;
    const float* Kg = base + D_MODEL;
    const float* Vg = base + 2 * D_MODEL;

    for (int idx = t; idx < 2048; idx += 256) {
        int r = idx >> 4, c4 = (idx & 15) * 4;
        float4 v = *(const float4*)(Qg + (size_t)(q0 + r) * QKV_W + c4);
        uint32_t ad = QH + (uint32_t)(r * AST + c4 * 2);
        asm volatile("st.shared.v2.b32 [%0], {%1, %2};" :: "r"(ad),
                     "r"(pack_hi(v.x, v.y)), "r"(pack_hi(v.z, v.w)) : "memory");
        asm volatile("st.shared.v2.b32 [%0], {%1, %2};" :: "r"(ad + AQ_MAT),
                     "r"(pack_lo(v.x, v.y)), "r"(pack_lo(v.z, v.w)) : "memory");
    }
    __syncthreads();

    uint32_t qfh[4][4], qfl[4][4];
#pragma unroll
    for (int ks = 0; ks < 4; ks++) {
        int row = wid * 16 + (lane & 15);
        int kcol = ks * 16 + (lane >> 4) * 8;
        uint32_t ad = QH + (uint32_t)(row * AST + kcol * 2);
        LDSM_X4(qfh[ks][0], qfh[ks][1], qfh[ks][2], qfh[ks][3], ad);
        LDSM_X4(qfl[ks][0], qfl[ks][1], qfl[ks][2], qfl[ks][3], ad + AQ_MAT);
    }

    float oacc[8][4];
#pragma unroll
    for (int nt = 0; nt < 8; nt++)
#pragma unroll
        for (int e = 0; e < 4; e++) oacc[nt][e] = 0.f;
    float mrow[2] = {-1e30f, -1e30f};
    float lrow[2] = {0.f, 0.f};

    int qmax = q0 + wid * 16 + 15;
    int NK = qt * 2 + 2;
    int qrow0 = q0 + wid * 16 + (lane >> 2);
    int lj = 2 * (lane & 3);

    for (int kt = 0; kt < NK; kt++) {
        __syncthreads();
        for (int idx = t; idx < 1024; idx += 256) {
            int r = idx >> 4, c4 = (idx & 15) * 4;
            size_t grow = (size_t)(kt * 64 + r) * QKV_W + c4;
            uint32_t ad = (uint32_t)(r * AST + c4 * 2);
            float4 kv = *(const float4*)(Kg + grow);
            asm volatile("st.shared.v2.b32 [%0], {%1, %2};" :: "r"(KH + ad),
                         "r"(pack_hi(kv.x, kv.y)), "r"(pack_hi(kv.z, kv.w)) : "memory");
            asm volatile("st.shared.v2.b32 [%0], {%1, %2};" :: "r"(KL + ad),
                         "r"(pack_lo(kv.x, kv.y)), "r"(pack_lo(kv.z, kv.w)) : "memory");
            float4 vv = *(const float4*)(Vg + grow);
            asm volatile("st.shared.v2.b32 [%0], {%1, %2};" :: "r"(VH + ad),
                         "r"(pack_hi(vv.x, vv.y)), "r"(pack_hi(vv.z, vv.w)) : "memory");
            asm volatile("st.shared.v2.b32 [%0], {%1, %2};" :: "r"(VL + ad),
                         "r"(pack_lo(vv.x, vv.y)), "r"(pack_lo(vv.z, vv.w)) : "memory");
        }
        __syncthreads();
        if (kt * 64 > qmax) continue;

        float sacc[8][4];
#pragma unroll
        for (int nt = 0; nt < 8; nt++)
#pragma unroll
            for (int e = 0; e < 4; e++) sacc[nt][e] = 0.f;
#pragma unroll
        for (int ks = 0; ks < 4; ks++) {
#pragma unroll
            for (int np = 0; np < 4; np++) {
                int nrow = np * 16 + (lane & 7) + ((lane >> 4) << 3);
                int kcol = ks * 16 + ((lane >> 3) & 1) * 8;
                uint32_t ad = KH + (uint32_t)(nrow * AST + kcol * 2);
                uint32_t bfh[4], bfl[4];
                LDSM_X4(bfh[0], bfh[1], bfh[2], bfh[3], ad);
                LDSM_X4(bfl[0], bfl[1], bfl[2], bfl[3], ad + AK_MAT);
                int nt0 = np * 2;
                MMA_BF16(sacc[nt0],   qfh[ks], bfh[0], bfh[1]);
                MMA_BF16(sacc[nt0+1], qfh[ks], bfh[2], bfh[3]);
                MMA_BF16(sacc[nt0],   qfh[ks], bfl[0], bfl[1]);
                MMA_BF16(sacc[nt0+1], qfh[ks], bfl[2], bfl[3]);
                MMA_BF16(sacc[nt0],   qfl[ks], bfh[0], bfh[1]);
                MMA_BF16(sacc[nt0+1], qfl[ks], bfh[2], bfh[3]);
            }
        }

        bool maskt = (kt >= NK - 2);
#pragma unroll
        for (int nt = 0; nt < 8; nt++) {
            int kgb = kt * 64 + nt * 8 + lj;
#pragma unroll
            for (int e = 0; e < 4; e++) {
                float s = sacc[nt][e] * 0.125f;
                if (maskt) {
                    int kg = kgb + (e & 1);
                    int qg = qrow0 + (e >> 1) * 8;
                    if (kg > qg) s = -1e30f;
                }
                sacc[nt][e] = s;
            }
        }

        float tm0 = -1e30f, tm1 = -1e30f;
#pragma unroll
        for (int nt = 0; nt < 8; nt++) {
            tm0 = fmaxf(tm0, fmaxf(sacc[nt][0], sacc[nt][1]));
            tm1 = fmaxf(tm1, fmaxf(sacc[nt][2], sacc[nt][3]));
        }
        tm0 = fmaxf(tm0, __shfl_xor_sync(0xffffffffu, tm0, 1));
        tm0 = fmaxf(tm0, __shfl_xor_sync(0xffffffffu, tm0, 2));
        tm1 = fmaxf(tm1, __shfl_xor_sync(0xffffffffu, tm1, 1));
        tm1 = fmaxf(tm1, __shfl_xor_sync(0xffffffffu, tm1, 2));
        float mn0 = fmaxf(mrow[0], tm0), mn1 = fmaxf(mrow[1], tm1);
        float al0 = __expf(mrow[0] - mn0), al1 = __expf(mrow[1] - mn1);
        mrow[0] = mn0; mrow[1] = mn1;

        float rs0 = 0.f, rs1 = 0.f;
#pragma unroll
        for (int nt = 0; nt < 8; nt++) {
            float p0 = __expf(sacc[nt][0] - mn0);
            float p1 = __expf(sacc[nt][1] - mn0);
            float p2 = __expf(sacc[nt][2] - mn1);
            float p3 = __expf(sacc[nt][3] - mn1);
            sacc[nt][0] = p0; sacc[nt][1] = p1; sacc[nt][2] = p2; sacc[nt][3] = p3;
            rs0 += p0 + p1; rs1 += p2 + p3;
        }
        rs0 += __shfl_xor_sync(0xffffffffu, rs0, 1);
        rs0 += __shfl_xor_sync(0xffffffffu, rs0, 2);
        rs1 += __shfl_xor_sync(0xffffffffu, rs1, 1);
        rs1 += __shfl_xor_sync(0xffffffffu, rs1, 2);
        lrow[0] = lrow[0] * al0 + rs0;
        lrow[1] = lrow[1] * al1 + rs1;
#pragma unroll
        for (int nt = 0; nt < 8; nt++) {
            oacc[nt][0] *= al0; oacc[nt][1] *= al0;
            oacc[nt][2] *= al1; oacc[nt][3] *= al1;
        }

#pragma unroll
        for (int kt2 = 0; kt2 < 4; kt2++) {
            uint32_t aPh[4], aPl[4];
            int n0i = 2 * kt2, n1i = 2 * kt2 + 1;
            aPh[0] = pack_hi(sacc[n0i][0], sacc[n0i][1]);
            aPh[1] = pack_hi(sacc[n0i][2], sacc[n0i][3]);
            aPh[2] = pack_hi(sacc[n1i][0], sacc[n1i][1]);
            aPh[3] = pack_hi(sacc[n1i][2], sacc[n1i][3]);
            aPl[0] = pack_lo(sacc[n0i][0], sacc[n0i][1]);
            aPl[1] = pack_lo(sacc[n0i][2], sacc[n0i][3]);
            aPl[2] = pack_lo(sacc[n1i][0], sacc[n1i][1]);
            aPl[3] = pack_lo(sacc[n1i][2], sacc[n1i][3]);
#pragma unroll
            for (int dp = 0; dp < 4; dp++) {
                int krow = kt2 * 16 + ((lane >> 3) & 1) * 8 + (lane & 7);
                int dbyte = dp * 32 + (lane >> 4) * 16;
                uint32_t ad = VH + (uint32_t)(krow * AST + dbyte);
                uint32_t vfh[4], vfl[4];
                LDSM_X4_T(vfh[0], vfh[1], vfh[2], vfh[3], ad);
                LDSM_X4_T(vfl[0], vfl[1], vfl[2], vfl[3], ad + AK_MAT);
                MMA_BF16(oacc[2*dp],   aPh, vfh[0], vfh[1]);
                MMA_BF16(oacc[2*dp+1], aPh, vfh[2], vfh[3]);
                MMA_BF16(oacc[2*dp],   aPh, vfl[0], vfl[1]);
                MMA_BF16(oacc[2*dp+1], aPh, vfl[2], vfl[3]);
                MMA_BF16(oacc[2*dp],   aPl, vfh[0], vfh[1]);
                MMA_BF16(oacc[2*dp+1], aPl, vfh[2], vfh[3]);
            }
        }
    }

    float inv0 = 1.f / lrow[0], inv1 = 1.f / lrow[1];
    size_t ob = ((size_t)b * SEQ + qrow0) * D_MODEL + h * HDIM;
#pragma unroll
    for (int nt = 0; nt < 8; nt++) {
        int cb = nt * 8 + lj;
        *(float2*)(O + ob + cb) = make_float2(oacc[nt][0] * inv0, oacc[nt][1] * inv0);
        *(float2*)(O + ob + 8 * D_MODEL + cb) = make_float2(oacc[nt][2] * inv1, oacc[nt][3] * inv1);
    }
}

// ================= launch =================
extern "C" void kernel_launch(void* const* d_in, const int* in_sizes, int n_in,
                              void* d_out, int out_size)
{
    (void)in_sizes; (void)n_in; (void)out_size;
    const float* x  = (const float*)d_in[0];
    const float* Wq = (const float*)d_in[1];
    const float* Wk = (const float*)d_in[2];
    const float* Wv = (const float*)d_in[3];
    const float* Wo = (const float*)d_in[4];
    const float* bo = (const float*)d_in[5];
    const float* W1 = (const float*)d_in[6];
    const float* b1 = (const float*)d_in[7];
    const float* W2 = (const float*)d_in[8];
    const float* b2 = (const float*)d_in[9];
    const float* g1 = (const float*)d_in[10];
    const float* s1 = (const float*)d_in[11];
    const float* g2 = (const float*)d_in[12];
    const float* s2 = (const float*)d_in[13];
    float* out = (float*)d_out;

    float *ln, *qkv, *ctx, *h, *f1, *wqkvT, *woT;
    __half *w1TH, *w1TL, *w2TH, *w2TL;
    cudaGetSymbolAddress((void**)&ln,    g_ln);
    cudaGetSymbolAddress((void**)&qkv,   g_qkv);
    cudaGetSymbolAddress((void**)&ctx,   g_ctx);
    cudaGetSymbolAddress((void**)&h,     g_h);
    cudaGetSymbolAddress((void**)&f1,    g_f1);
    cudaGetSymbolAddress((void**)&wqkvT, g_wqkvT);
    cudaGetSymbolAddress((void**)&woT,   g_woT);
    cudaGetSymbolAddress((void**)&w1TH,  g_w1TH);
    cudaGetSymbolAddress((void**)&w1TL,  g_w1TL);
    cudaGetSymbolAddress((void**)&w2TH,  g_w2TH);
    cudaGetSymbolAddress((void**)&w2TL,  g_w2TL);

    cudaFuncSetAttribute(gemm_mma<0>, cudaFuncAttributeMaxDynamicSharedMemorySize, GEMM_SMEM);
    cudaFuncSetAttribute(gemm_mma<1>, cudaFuncAttributeMaxDynamicSharedMemorySize, GEMM_SMEM);
    cudaFuncSetAttribute(gemm2<1>, cudaFuncAttributeMaxDynamicSharedMemorySize, GEMM2_SMEM);
    cudaFuncSetAttribute(gemm2<2>, cudaFuncAttributeMaxDynamicSharedMemorySize, GEMM2_SMEM);
    cudaFuncSetAttribute(attn_mma, cudaFuncAttributeMaxDynamicSharedMemorySize, ATT_SMEM);

    dim3 tb(32, 8);
    transpose_kernel<<<dim3(D_MODEL/32, D_MODEL/32), tb>>>(Wq, wqkvT,                        D_MODEL, D_MODEL);
    transpose_kernel<<<dim3(D_MODEL/32, D_MODEL/32), tb>>>(Wk, wqkvT + 1024*(size_t)D_MODEL, D_MODEL, D_MODEL);
    transpose_kernel<<<dim3(D_MODEL/32, D_MODEL/32), tb>>>(Wv, wqkvT + 2048*(size_t)D_MODEL, D_MODEL, D_MODEL);
    transpose_kernel<<<dim3(D_MODEL/32, D_MODEL/32), tb>>>(Wo, woT, D_MODEL, D_MODEL);
    transpose_split_h<<<dim3(DFF/32,     D_MODEL/32), tb>>>(W1, w1TH, w1TL, D_MODEL, DFF);
    transpose_split_h<<<dim3(D_MODEL/32, DFF/32),     tb>>>(W2, w2TH, w2TL, DFF, D_MODEL);

    // 1. ln1 = LN(x)
    ln_kernel<<<NTOK, 256>>>(x, g1, s1, ln);
    // 2. qkv = ln1 @ [Wq|Wk|Wv]  (bf16 3-product)
    gemm_mma<0><<<dim3(QKV_W/128, NTOK/128), 256, GEMM_SMEM>>>(ln, wqkvT, nullptr, nullptr, qkv, NTOK, QKV_W, D_MODEL);
    // 3. causal attention
    attn_mma<<<dim3(SEQ/128, BATCH*NHEADS), 256, ATT_SMEM>>>(qkv, ctx);
    // 4. h = x + ctx @ Wo + bo   (bf16 3-product)
    gemm_mma<1><<<dim3(D_MODEL/128, NTOK/128), 256, GEMM_SMEM>>>(ctx, woT, bo, x, h, NTOK, D_MODEL, D_MODEL);
    // 5. ln2 = LN(h)
    ln_kernel<<<NTOK, 256>>>(h, g2, s2, ln);
    // 6. f1 = gelu(ln2 @ W1 + b1)  (fp16 2-product)
    gemm2<2><<<dim3(DFF/128, NTOK/128), 256, GEMM2_SMEM>>>(ln, w1TH, w1TL, b1, nullptr, f1, NTOK, DFF, D_MODEL);
    // 7. out = h + f1 @ W2 + b2    (fp16 2-product)
    gemm2<1><<<dim3(D_MODEL/128, NTOK/128), 256, GEMM2_SMEM>>>(f1, w2TH, w2TL, b2, h, out, NTOK, D_MODEL, DFF);
}

// round 8
// speedup vs baseline: 1.6317x; 1.2852x over previous
#include <cuda_runtime.h>
#include <cuda_fp16.h>
#include <cstdint>
#include <math.h>

#define D_MODEL 1024
#define DFF     4096
#define SEQ     2048
#define BATCH   2
#define NTOK    (SEQ*BATCH)      // 4096
#define NHEADS  16
#define HDIM    64
#define QKV_W   3072

// ---------------- scratch ----------------
__device__ float  g_ln  [NTOK*(size_t)D_MODEL];
__device__ float  g_qkv [NTOK*(size_t)QKV_W];
__device__ float  g_ctx [NTOK*(size_t)D_MODEL];
__device__ float  g_h   [NTOK*(size_t)D_MODEL];
__device__ float  g_f1  [NTOK*(size_t)DFF];
__device__ __half g_wqkvTH[(size_t)QKV_W*D_MODEL];
__device__ __half g_wqkvTL[(size_t)QKV_W*D_MODEL];
__device__ __half g_woTH  [(size_t)D_MODEL*D_MODEL];
__device__ __half g_woTL  [(size_t)D_MODEL*D_MODEL];
__device__ __half g_w1TH  [(size_t)DFF*D_MODEL];
__device__ __half g_w1TL  [(size_t)DFF*D_MODEL];
__device__ __half g_w2TH  [(size_t)D_MODEL*DFF];
__device__ __half g_w2TL  [(size_t)D_MODEL*DFF];

// ================= helpers =================
__device__ __forceinline__ uint32_t smem_u32(const void* p) {
    uint32_t a;
    asm("{ .reg .u64 t; cvta.to.shared.u64 t, %1; cvt.u32.u64 %0, t; }" : "=r"(a) : "l"(p));
    return a;
}

#define LDSM_X4(r0,r1,r2,r3,a) \
    asm volatile("ldmatrix.sync.aligned.m8n8.x4.shared.b16 {%0,%1,%2,%3}, [%4];" \
        : "=r"(r0), "=r"(r1), "=r"(r2), "=r"(r3) : "r"(a))
#define LDSM_X4_T(r0,r1,r2,r3,a) \
    asm volatile("ldmatrix.sync.aligned.m8n8.x4.trans.shared.b16 {%0,%1,%2,%3}, [%4];" \
        : "=r"(r0), "=r"(r1), "=r"(r2), "=r"(r3) : "r"(a))

#define MMA_F16(c, a, b0, b1) \
    asm volatile("mma.sync.aligned.m16n8k16.row.col.f32.f16.f16.f32 " \
        "{%0,%1,%2,%3}, {%4,%5,%6,%7}, {%8,%9}, {%0,%1,%2,%3};" \
        : "+f"((c)[0]), "+f"((c)[1]), "+f"((c)[2]), "+f"((c)[3]) \
        : "r"((a)[0]), "r"((a)[1]), "r"((a)[2]), "r"((a)[3]), "r"(b0), "r"(b1))

__device__ __forceinline__ uint32_t pack_h2(float a, float b) {
    __half2 t; t.x = __float2half_rn(a); t.y = __float2half_rn(b);
    return *(uint32_t*)&t;
}
__device__ __forceinline__ uint32_t pack_lo_h2(float a, float b) {
    __half ha = __float2half_rn(a), hb = __float2half_rn(b);
    __half2 t;
    t.x = __float2half_rn(a - __half2float(ha));
    t.y = __float2half_rn(b - __half2float(hb));
    return *(uint32_t*)&t;
}
__device__ __forceinline__ void cp16(uint32_t dst, const void* src) {
    asm volatile("cp.async.cg.shared.global [%0], [%1], 16;" :: "r"(dst), "l"(src));
}

// ================= weight transpose+split fp16: in[R,C] -> outH/outL[C,R] =====
__global__ void __launch_bounds__(256) transpose_split_h(
    const float* __restrict__ in, __half* __restrict__ outH, __half* __restrict__ outL,
    int R, int C)
{
    __shared__ float tile[32][33];
    int tx = threadIdx.x, ty = threadIdx.y;
    int x = blockIdx.x * 32 + tx;
    int y0 = blockIdx.y * 32;
#pragma unroll
    for (int i = ty; i < 32; i += 8)
        tile[i][tx] = in[(size_t)(y0 + i) * C + x];
    __syncthreads();
    int xo = y0 + tx;
    int y1 = blockIdx.x * 32;
#pragma unroll
    for (int i = ty; i < 32; i += 8) {
        float v = tile[tx][i];
        __half h = __float2half_rn(v);
        outH[(size_t)(y1 + i) * R + xo] = h;
        outL[(size_t)(y1 + i) * R + xo] = __float2half_rn(v - __half2float(h));
    }
}

// ================= layernorm =================
__global__ void __launch_bounds__(256) ln_kernel(const float* __restrict__ in,
                                                 const float* __restrict__ gamma,
                                                 const float* __restrict__ beta,
                                                 float* __restrict__ out)
{
    int row = blockIdx.x;
    const float* x = in + (size_t)row * D_MODEL;
    int t = threadIdx.x;
    float v[4];
    float s = 0.f;
#pragma unroll
    for (int i = 0; i < 4; i++) { v[i] = x[i*256 + t]; s += v[i]; }

    __shared__ float red[8];
    __shared__ float bcast;
#pragma unroll
    for (int o = 16; o > 0; o >>= 1) s += __shfl_xor_sync(0xffffffffu, s, o);
    if ((t & 31) == 0) red[t >> 5] = s;
    __syncthreads();
    if (t < 32) {
        float r = (t < 8) ? red[t] : 0.f;
#pragma unroll
        for (int o = 4; o > 0; o >>= 1) r += __shfl_xor_sync(0xffffffffu, r, o);
        if (t == 0) bcast = r;
    }
    __syncthreads();
    float mean = bcast * (1.f / D_MODEL);

    float s2 = 0.f;
#pragma unroll
    for (int i = 0; i < 4; i++) { float d = v[i] - mean; s2 += d*d; }
#pragma unroll
    for (int o = 16; o > 0; o >>= 1) s2 += __shfl_xor_sync(0xffffffffu, s2, o);
    __syncthreads();
    if ((t & 31) == 0) red[t >> 5] = s2;
    __syncthreads();
    if (t < 32) {
        float r = (t < 8) ? red[t] : 0.f;
#pragma unroll
        for (int o = 4; o > 0; o >>= 1) r += __shfl_xor_sync(0xffffffffu, r, o);
        if (t == 0) bcast = r;
    }
    __syncthreads();
    float rstd = rsqrtf(bcast * (1.f / D_MODEL) + 1e-5f);

#pragma unroll
    for (int i = 0; i < 4; i++) {
        int d = i*256 + t;
        out[(size_t)row * D_MODEL + d] = gamma[d] * (v[i] - mean) * rstd + beta[d];
    }
}

// ================= GEMM common epilogue =================
template<int EPI>
__device__ __forceinline__ void gemm_epilogue(
    float acc[2][8][4], const float* bias, const float* res, float* C,
    int m0, int n0, int warp_m, int warp_n, int lane, int N)
{
    int g   = lane >> 2;
    int tig = lane & 3;
#pragma unroll
    for (int mt = 0; mt < 2; mt++) {
#pragma unroll
        for (int nt = 0; nt < 8; nt++) {
            int col = n0 + warp_n * 64 + nt * 8 + 2 * tig;
            int row0 = m0 + warp_m * 32 + mt * 16 + g;
            int row1 = row0 + 8;
            float v00 = acc[mt][nt][0], v01 = acc[mt][nt][1];
            float v10 = acc[mt][nt][2], v11 = acc[mt][nt][3];
            if (EPI != 0) {
                float b0 = bias[col], b1 = bias[col + 1];
                v00 += b0; v01 += b1; v10 += b0; v11 += b1;
            }
            if (EPI == 2) {
                float vv[4] = {v00, v01, v10, v11};
#pragma unroll
                for (int q = 0; q < 4; q++) {
                    float xx = vv[q];
                    float u = 0.7978845608028654f * (xx + 0.044715f * xx * xx * xx);
                    vv[q] = 0.5f * xx * (1.f + tanhf(u));
                }
                v00 = vv[0]; v01 = vv[1]; v10 = vv[2]; v11 = vv[3];
            }
            if (EPI == 1) {
                float2 r0 = *(const float2*)(res + (size_t)row0 * N + col);
                float2 r1 = *(const float2*)(res + (size_t)row1 * N + col);
                v00 += r0.x; v01 += r0.y; v10 += r1.x; v11 += r1.y;
            }
            *(float2*)(C + (size_t)row0 * N + col) = make_float2(v00, v01);
            *(float2*)(C + (size_t)row1 * N + col) = make_float2(v10, v11);
        }
    }
}

// ================= fp16 2-product GEMM (proven R7) =================
// C = A(fp32,[M,K]) @ Bt^T with Bt pre-split fp16 (Bh,Bl)[N,K].
#define ROW_BYTES  80
#define MAT_BYTES  (128*ROW_BYTES)
#define STAGE2_BYTES (3*MAT_BYTES)       // 30720
#define GEMM2_SMEM   (2*STAGE2_BYTES)    // 61440

template<int EPI>   // 0=plain, 1=bias+res, 2=bias+gelu
__global__ void __launch_bounds__(256) gemm2(
    const float* __restrict__ A,
    const __half* __restrict__ Bh, const __half* __restrict__ Bl,
    const float* __restrict__ bias, const float* __restrict__ res,
    float* __restrict__ C, int M, int N, int K)
{
    extern __shared__ char dynsm[];
    uint32_t sbase = smem_u32(dynsm);

    int t = threadIdx.x;
    int lane = t & 31, wid = t >> 5;
    int warp_m = wid & 3;
    int warp_n = wid >> 2;
    int m0 = blockIdx.y * 128, n0 = blockIdx.x * 128;
    const int NC = K >> 5;

    const float* Ap = A + (size_t)m0 * K;
    const __half* Bsrc[2] = { Bh + (size_t)n0 * K, Bl + (size_t)n0 * K };

    int lrow  = t >> 3;
    int lcol4 = (t & 7) * 4;
    int brow  = t >> 2;
    int bq    = t & 3;

    float acc[2][8][4];
#pragma unroll
    for (int mt = 0; mt < 2; mt++)
#pragma unroll
        for (int nt = 0; nt < 8; nt++)
#pragma unroll
            for (int r = 0; r < 4; r++) acc[mt][nt][r] = 0.f;

    auto issue_B = [&](int st, int k0) {
#pragma unroll
        for (int m = 0; m < 2; m++) {
#pragma unroll
            for (int i = 0; i < 2; i++) {
                int row = brow + i * 64;
                uint32_t dst = sbase + (uint32_t)(st * STAGE2_BYTES + (1 + m) * MAT_BYTES
                                                  + row * ROW_BYTES + bq * 16);
                cp16(dst, Bsrc[m] + (size_t)row * K + k0 + bq * 8);
            }
        }
        asm volatile("cp.async.commit_group;");
    };

    auto sts_A = [&](int st, int row, int col4, float4 v) {
        uint32_t ad = sbase + (uint32_t)(st * STAGE2_BYTES + row * ROW_BYTES + col4 * 2);
        asm volatile("st.shared.v2.b32 [%0], {%1, %2};" :: "r"(ad),
                     "r"(pack_h2(v.x, v.y)), "r"(pack_h2(v.z, v.w)) : "memory");
    };

    auto compute_stage = [&](int st) {
        uint32_t stb = sbase + (uint32_t)st * STAGE2_BYTES;
        uint32_t bh_base = stb + MAT_BYTES;
#pragma unroll
        for (int ks = 0; ks < 2; ks++) {
            uint32_t af[2][4];
#pragma unroll
            for (int mt = 0; mt < 2; mt++) {
                int row = warp_m * 32 + mt * 16 + (lane & 15);
                int kcol = ks * 16 + (lane >> 4) * 8;
                uint32_t addr = stb + (uint32_t)(row * ROW_BYTES + kcol * 2);
                LDSM_X4(af[mt][0], af[mt][1], af[mt][2], af[mt][3], addr);
            }
#pragma unroll
            for (int np = 0; np < 4; np++) {
                int nrow = warp_n * 64 + np * 16 + (lane & 7) + ((lane >> 4) << 3);
                int kcol = ks * 16 + ((lane >> 3) & 1) * 8;
                uint32_t addr = bh_base + (uint32_t)(nrow * ROW_BYTES + kcol * 2);
                uint32_t bfh[4], bfl[4];
                LDSM_X4(bfh[0], bfh[1], bfh[2], bfh[3], addr);
                LDSM_X4(bfl[0], bfl[1], bfl[2], bfl[3], addr + MAT_BYTES);
#pragma unroll
                for (int mt = 0; mt < 2; mt++) {
                    int nt0 = np * 2;
                    MMA_F16(acc[mt][nt0],   af[mt], bfh[0], bfh[1]);
                    MMA_F16(acc[mt][nt0+1], af[mt], bfh[2], bfh[3]);
                    MMA_F16(acc[mt][nt0],   af[mt], bfl[0], bfl[1]);
                    MMA_F16(acc[mt][nt0+1], af[mt], bfl[2], bfl[3]);
                }
            }
        }
    };

    issue_B(0, 0);
    {
#pragma unroll
        for (int i = 0; i < 4; i++) {
            int row = lrow + i * 32;
            float4 a4 = *(const float4*)(Ap + (size_t)row * K + lcol4);
            sts_A(0, row, lcol4, a4);
        }
    }
    asm volatile("cp.async.wait_group 0;");
    __syncthreads();

    for (int c = 0; c < NC; c++) {
        int st = c & 1;
        bool has_next = (c + 1 < NC);
        float4 abuf[4];
        if (has_next) {
            int k0 = (c + 1) * 32;
            issue_B(1 - st, k0);
#pragma unroll
            for (int i = 0; i < 4; i++) {
                int row = lrow + i * 32;
                abuf[i] = *(const float4*)(Ap + (size_t)row * K + k0 + lcol4);
            }
        }
        compute_stage(st);
        if (has_next) {
#pragma unroll
            for (int i = 0; i < 4; i++) {
                int row = lrow + i * 32;
                sts_A(1 - st, row, lcol4, abuf[i]);
            }
        }
        asm volatile("cp.async.wait_group 0;");
        __syncthreads();
    }

    gemm_epilogue<EPI>(acc, bias, res, C, m0, n0, warp_m, warp_n, lane, N);
}

// ================= tensor-core flash attention (fp16 2-product) =================
// Q single fp16; K,V split hi/lo fp16; P single fp16.
#define AST 144
#define AQ_MAT (128*AST)       // 18432
#define AK_MAT (64*AST)        // 9216
#define ATT_SMEM (AQ_MAT + 4*AK_MAT)   // 55296

__global__ void __launch_bounds__(256) attn_mma(
    const float* __restrict__ QKV, float* __restrict__ O)
{
    extern __shared__ char asmem[];
    uint32_t sb = smem_u32(asmem);
    const uint32_t QF = sb;
    const uint32_t KH = sb + AQ_MAT, KL = KH + AK_MAT;
    const uint32_t VH = KL + AK_MAT, VL = VH + AK_MAT;

    int t = threadIdx.x, lane = t & 31, wid = t >> 5;
    int qt = blockIdx.x, bh = blockIdx.y;
    int b = bh >> 4, h = bh & 15;
    int q0 = qt * 128;

    const float* base = QKV + (size_t)b * SEQ * QKV_W + h * HDIM;
    const float* Qg = base;
    const float* Kg = base + D_MODEL;
    const float* Vg = base + 2 * D_MODEL;

    // ---- load Q tile (128 x 64) single fp16 ----
    for (int idx = t; idx < 2048; idx += 256) {
        int r = idx >> 4, c4 = (idx & 15) * 4;
        float4 v = *(const float4*)(Qg + (size_t)(q0 + r) * QKV_W + c4);
        uint32_t ad = QF + (uint32_t)(r * AST + c4 * 2);
        asm volatile("st.shared.v2.b32 [%0], {%1, %2};" :: "r"(ad),
                     "r"(pack_h2(v.x, v.y)), "r"(pack_h2(v.z, v.w)) : "memory");
    }
    __syncthreads();

    uint32_t qf[4][4];
#pragma unroll
    for (int ks = 0; ks < 4; ks++) {
        int row = wid * 16 + (lane & 15);
        int kcol = ks * 16 + (lane >> 4) * 8;
        uint32_t ad = QF + (uint32_t)(row * AST + kcol * 2);
        LDSM_X4(qf[ks][0], qf[ks][1], qf[ks][2], qf[ks][3], ad);
    }

    float oacc[8][4];
#pragma unroll
    for (int nt = 0; nt < 8; nt++)
#pragma unroll
        for (int e = 0; e < 4; e++) oacc[nt][e] = 0.f;
    float mrow[2] = {-1e30f, -1e30f};
    float lrow[2] = {0.f, 0.f};

    int qmax = q0 + wid * 16 + 15;
    int NK = qt * 2 + 2;
    int qrow0 = q0 + wid * 16 + (lane >> 2);
    int lj = 2 * (lane & 3);

    for (int kt = 0; kt < NK; kt++) {
        __syncthreads();
        for (int idx = t; idx < 1024; idx += 256) {
            int r = idx >> 4, c4 = (idx & 15) * 4;
            size_t grow = (size_t)(kt * 64 + r) * QKV_W + c4;
            uint32_t ad = (uint32_t)(r * AST + c4 * 2);
            float4 kv = *(const float4*)(Kg + grow);
            asm volatile("st.shared.v2.b32 [%0], {%1, %2};" :: "r"(KH + ad),
                         "r"(pack_h2(kv.x, kv.y)), "r"(pack_h2(kv.z, kv.w)) : "memory");
            asm volatile("st.shared.v2.b32 [%0], {%1, %2};" :: "r"(KL + ad),
                         "r"(pack_lo_h2(kv.x, kv.y)), "r"(pack_lo_h2(kv.z, kv.w)) : "memory");
            float4 vv = *(const float4*)(Vg + grow);
            asm volatile("st.shared.v2.b32 [%0], {%1, %2};" :: "r"(VH + ad),
                         "r"(pack_h2(vv.x, vv.y)), "r"(pack_h2(vv.z, vv.w)) : "memory");
            asm volatile("st.shared.v2.b32 [%0], {%1, %2};" :: "r"(VL + ad),
                         "r"(pack_lo_h2(vv.x, vv.y)), "r"(pack_lo_h2(vv.z, vv.w)) : "memory");
        }
        __syncthreads();
        if (kt * 64 > qmax) continue;

        // ---- S = Q K^T (2-product) ----
        float sacc[8][4];
#pragma unroll
        for (int nt = 0; nt < 8; nt++)
#pragma unroll
            for (int e = 0; e < 4; e++) sacc[nt][e] = 0.f;
#pragma unroll
        for (int ks = 0; ks < 4; ks++) {
#pragma unroll
            for (int np = 0; np < 4; np++) {
                int nrow = np * 16 + (lane & 7) + ((lane >> 4) << 3);
                int kcol = ks * 16 + ((lane >> 3) & 1) * 8;
                uint32_t ad = KH + (uint32_t)(nrow * AST + kcol * 2);
                uint32_t bfh[4], bfl[4];
                LDSM_X4(bfh[0], bfh[1], bfh[2], bfh[3], ad);
                LDSM_X4(bfl[0], bfl[1], bfl[2], bfl[3], ad + AK_MAT);
                int nt0 = np * 2;
                MMA_F16(sacc[nt0],   qf[ks], bfh[0], bfh[1]);
                MMA_F16(sacc[nt0+1], qf[ks], bfh[2], bfh[3]);
                MMA_F16(sacc[nt0],   qf[ks], bfl[0], bfl[1]);
                MMA_F16(sacc[nt0+1], qf[ks], bfl[2], bfl[3]);
            }
        }

        bool maskt = (kt >= NK - 2);
#pragma unroll
        for (int nt = 0; nt < 8; nt++) {
            int kgb = kt * 64 + nt * 8 + lj;
#pragma unroll
            for (int e = 0; e < 4; e++) {
                float s = sacc[nt][e] * 0.125f;
                if (maskt) {
                    int kg = kgb + (e & 1);
                    int qg = qrow0 + (e >> 1) * 8;
                    if (kg > qg) s = -1e30f;
                }
                sacc[nt][e] = s;
            }
        }

        float tm0 = -1e30f, tm1 = -1e30f;
#pragma unroll
        for (int nt = 0; nt < 8; nt++) {
            tm0 = fmaxf(tm0, fmaxf(sacc[nt][0], sacc[nt][1]));
            tm1 = fmaxf(tm1, fmaxf(sacc[nt][2], sacc[nt][3]));
        }
        tm0 = fmaxf(tm0, __shfl_xor_sync(0xffffffffu, tm0, 1));
        tm0 = fmaxf(tm0, __shfl_xor_sync(0xffffffffu, tm0, 2));
        tm1 = fmaxf(tm1, __shfl_xor_sync(0xffffffffu, tm1, 1));
        tm1 = fmaxf(tm1, __shfl_xor_sync(0xffffffffu, tm1, 2));
        float mn0 = fmaxf(mrow[0], tm0), mn1 = fmaxf(mrow[1], tm1);
        float al0 = __expf(mrow[0] - mn0), al1 = __expf(mrow[1] - mn1);
        mrow[0] = mn0; mrow[1] = mn1;

        float rs0 = 0.f, rs1 = 0.f;
#pragma unroll
        for (int nt = 0; nt < 8; nt++) {
            float p0 = __expf(sacc[nt][0] - mn0);
            float p1 = __expf(sacc[nt][1] - mn0);
            float p2 = __expf(sacc[nt][2] - mn1);
            float p3 = __expf(sacc[nt][3] - mn1);
            sacc[nt][0] = p0; sacc[nt][1] = p1; sacc[nt][2] = p2; sacc[nt][3] = p3;
            rs0 += p0 + p1; rs1 += p2 + p3;
        }
        rs0 += __shfl_xor_sync(0xffffffffu, rs0, 1);
        rs0 += __shfl_xor_sync(0xffffffffu, rs0, 2);
        rs1 += __shfl_xor_sync(0xffffffffu, rs1, 1);
        rs1 += __shfl_xor_sync(0xffffffffu, rs1, 2);
        lrow[0] = lrow[0] * al0 + rs0;
        lrow[1] = lrow[1] * al1 + rs1;
#pragma unroll
        for (int nt = 0; nt < 8; nt++) {
            oacc[nt][0] *= al0; oacc[nt][1] *= al0;
            oacc[nt][2] *= al1; oacc[nt][3] *= al1;
        }

        // ---- O += P V (P single fp16, V hi/lo) ----
#pragma unroll
        for (int kt2 = 0; kt2 < 4; kt2++) {
            uint32_t aP[4];
            int n0i = 2 * kt2, n1i = 2 * kt2 + 1;
            aP[0] = pack_h2(sacc[n0i][0], sacc[n0i][1]);
            aP[1] = pack_h2(sacc[n0i][2], sacc[n0i][3]);
            aP[2] = pack_h2(sacc[n1i][0], sacc[n1i][1]);
            aP[3] = pack_h2(sacc[n1i][2], sacc[n1i][3]);
#pragma unroll
            for (int dp = 0; dp < 4; dp++) {
                int krow = kt2 * 16 + ((lane >> 3) & 1) * 8 + (lane & 7);
                int dbyte = dp * 32 + (lane >> 4) * 16;
                uint32_t ad = VH + (uint32_t)(krow * AST + dbyte);
                uint32_t vfh[4], vfl[4];
                LDSM_X4_T(vfh[0], vfh[1], vfh[2], vfh[3], ad);
                LDSM_X4_T(vfl[0], vfl[1], vfl[2], vfl[3], ad + AK_MAT);
                MMA_F16(oacc[2*dp],   aP, vfh[0], vfh[1]);
                MMA_F16(oacc[2*dp+1], aP, vfh[2], vfh[3]);
                MMA_F16(oacc[2*dp],   aP, vfl[0], vfl[1]);
                MMA_F16(oacc[2*dp+1], aP, vfl[2], vfl[3]);
            }
        }
    }

    float inv0 = 1.f / lrow[0], inv1 = 1.f / lrow[1];
    size_t ob = ((size_t)b * SEQ + qrow0) * D_MODEL + h * HDIM;
#pragma unroll
    for (int nt = 0; nt < 8; nt++) {
        int cb = nt * 8 + lj;
        *(float2*)(O + ob + cb) = make_float2(oacc[nt][0] * inv0, oacc[nt][1] * inv0);
        *(float2*)(O + ob + 8 * D_MODEL + cb) = make_float2(oacc[nt][2] * inv1, oacc[nt][3] * inv1);
    }
}

// ================= launch =================
extern "C" void kernel_launch(void* const* d_in, const int* in_sizes, int n_in,
                              void* d_out, int out_size)
{
    (void)in_sizes; (void)n_in; (void)out_size;
    const float* x  = (const float*)d_in[0];
    const float* Wq = (const float*)d_in[1];
    const float* Wk = (const float*)d_in[2];
    const float* Wv = (const float*)d_in[3];
    const float* Wo = (const float*)d_in[4];
    const float* bo = (const float*)d_in[5];
    const float* W1 = (const float*)d_in[6];
    const float* b1 = (const float*)d_in[7];
    const float* W2 = (const float*)d_in[8];
    const float* b2 = (const float*)d_in[9];
    const float* g1 = (const float*)d_in[10];
    const float* s1 = (const float*)d_in[11];
    const float* g2 = (const float*)d_in[12];
    const float* s2 = (const float*)d_in[13];
    float* out = (float*)d_out;

    float *ln, *qkv, *ctx, *h, *f1;
    __half *wqkvTH, *wqkvTL, *woTH, *woTL, *w1TH, *w1TL, *w2TH, *w2TL;
    cudaGetSymbolAddress((void**)&ln,     g_ln);
    cudaGetSymbolAddress((void**)&qkv,    g_qkv);
    cudaGetSymbolAddress((void**)&ctx,    g_ctx);
    cudaGetSymbolAddress((void**)&h,      g_h);
    cudaGetSymbolAddress((void**)&f1,     g_f1);
    cudaGetSymbolAddress((void**)&wqkvTH, g_wqkvTH);
    cudaGetSymbolAddress((void**)&wqkvTL, g_wqkvTL);
    cudaGetSymbolAddress((void**)&woTH,   g_woTH);
    cudaGetSymbolAddress((void**)&woTL,   g_woTL);
    cudaGetSymbolAddress((void**)&w1TH,   g_w1TH);
    cudaGetSymbolAddress((void**)&w1TL,   g_w1TL);
    cudaGetSymbolAddress((void**)&w2TH,   g_w2TH);
    cudaGetSymbolAddress((void**)&w2TL,   g_w2TL);

    cudaFuncSetAttribute(gemm2<0>, cudaFuncAttributeMaxDynamicSharedMemorySize, GEMM2_SMEM);
    cudaFuncSetAttribute(gemm2<1>, cudaFuncAttributeMaxDynamicSharedMemorySize, GEMM2_SMEM);
    cudaFuncSetAttribute(gemm2<2>, cudaFuncAttributeMaxDynamicSharedMemorySize, GEMM2_SMEM);
    cudaFuncSetAttribute(attn_mma, cudaFuncAttributeMaxDynamicSharedMemorySize, ATT_SMEM);

    dim3 tb(32, 8);
    transpose_split_h<<<dim3(D_MODEL/32, D_MODEL/32), tb>>>(Wq, wqkvTH,                        wqkvTL,                        D_MODEL, D_MODEL);
    transpose_split_h<<<dim3(D_MODEL/32, D_MODEL/32), tb>>>(Wk, wqkvTH + 1024*(size_t)D_MODEL, wqkvTL + 1024*(size_t)D_MODEL, D_MODEL, D_MODEL);
    transpose_split_h<<<dim3(D_MODEL/32, D_MODEL/32), tb>>>(Wv, wqkvTH + 2048*(size_t)D_MODEL, wqkvTL + 2048*(size_t)D_MODEL, D_MODEL, D_MODEL);
    transpose_split_h<<<dim3(D_MODEL/32, D_MODEL/32), tb>>>(Wo, woTH, woTL, D_MODEL, D_MODEL);
    transpose_split_h<<<dim3(DFF/32,     D_MODEL/32), tb>>>(W1, w1TH, w1TL, D_MODEL, DFF);
    transpose_split_h<<<dim3(D_MODEL/32, DFF/32),     tb>>>(W2, w2TH, w2TL, DFF, D_MODEL);

    // 1. ln1 = LN(x)
    ln_kernel<<<NTOK, 256>>>(x, g1, s1, ln);
    // 2. qkv = ln1 @ [Wq|Wk|Wv]
    gemm2<0><<<dim3(QKV_W/128, NTOK/128), 256, GEMM2_SMEM>>>(ln, wqkvTH, wqkvTL, nullptr, nullptr, qkv, NTOK, QKV_W, D_MODEL);
    // 3. causal attention
    attn_mma<<<dim3(SEQ/128, BATCH*NHEADS), 256, ATT_SMEM>>>(qkv, ctx);
    // 4. h = x + ctx @ Wo + bo
    gemm2<1><<<dim3(D_MODEL/128, NTOK/128), 256, GEMM2_SMEM>>>(ctx, woTH, woTL, bo, x, h, NTOK, D_MODEL, D_MODEL);
    // 5. ln2 = LN(h)
    ln_kernel<<<NTOK, 256>>>(h, g2, s2, ln);
    // 6. f1 = gelu(ln2 @ W1 + b1)
    gemm2<2><<<dim3(DFF/128, NTOK/128), 256, GEMM2_SMEM>>>(ln, w1TH, w1TL, b1, nullptr, f1, NTOK, DFF, D_MODEL);
    // 7. out = h + f1 @ W2 + b2
    gemm2<1><<<dim3(D_MODEL/128, NTOK/128), 256, GEMM2_SMEM>>>(f1, w2TH, w2TL, b2, h, out, NTOK, D_MODEL, DFF);
}

// round 9
// speedup vs baseline: 2.2447x; 1.3757x over previous
#include <cuda_runtime.h>
#include <cuda_fp16.h>
#include <cstdint>
#include <math.h>

#define D_MODEL 1024
#define DFF     4096
#define SEQ     2048
#define BATCH   2
#define NTOK    (SEQ*BATCH)      // 4096
#define NHEADS  16
#define HDIM    64
#define QKV_W   3072

// ---------------- scratch ----------------
__device__ float  g_ln  [NTOK*(size_t)D_MODEL];
__device__ float  g_qkv [NTOK*(size_t)QKV_W];
__device__ float  g_ctx [NTOK*(size_t)D_MODEL];
__device__ float  g_h   [NTOK*(size_t)D_MODEL];
__device__ float  g_f1  [NTOK*(size_t)DFF];
__device__ __half g_wqkvT[(size_t)QKV_W*D_MODEL];
__device__ __half g_woT  [(size_t)D_MODEL*D_MODEL];
__device__ __half g_w1T  [(size_t)DFF*D_MODEL];
__device__ __half g_w2T  [(size_t)D_MODEL*DFF];

// ================= helpers =================
__device__ __forceinline__ uint32_t smem_u32(const void* p) {
    uint32_t a;
    asm("{ .reg .u64 t; cvta.to.shared.u64 t, %1; cvt.u32.u64 %0, t; }" : "=r"(a) : "l"(p));
    return a;
}

#define LDSM_X4(r0,r1,r2,r3,a) \
    asm volatile("ldmatrix.sync.aligned.m8n8.x4.shared.b16 {%0,%1,%2,%3}, [%4];" \
        : "=r"(r0), "=r"(r1), "=r"(r2), "=r"(r3) : "r"(a))
#define LDSM_X4_T(r0,r1,r2,r3,a) \
    asm volatile("ldmatrix.sync.aligned.m8n8.x4.trans.shared.b16 {%0,%1,%2,%3}, [%4];" \
        : "=r"(r0), "=r"(r1), "=r"(r2), "=r"(r3) : "r"(a))

#define MMA_F16(c, a, b0, b1) \
    asm volatile("mma.sync.aligned.m16n8k16.row.col.f32.f16.f16.f32 " \
        "{%0,%1,%2,%3}, {%4,%5,%6,%7}, {%8,%9}, {%0,%1,%2,%3};" \
        : "+f"((c)[0]), "+f"((c)[1]), "+f"((c)[2]), "+f"((c)[3]) \
        : "r"((a)[0]), "r"((a)[1]), "r"((a)[2]), "r"((a)[3]), "r"(b0), "r"(b1))

__device__ __forceinline__ uint32_t pack_h2(float a, float b) {
    __half2 t; t.x = __float2half_rn(a); t.y = __float2half_rn(b);
    return *(uint32_t*)&t;
}
__device__ __forceinline__ uint32_t pack_lo_h2(float a, float b) {
    __half ha = __float2half_rn(a), hb = __float2half_rn(b);
    __half2 t;
    t.x = __float2half_rn(a - __half2float(ha));
    t.y = __float2half_rn(b - __half2float(hb));
    return *(uint32_t*)&t;
}
__device__ __forceinline__ void cp16(uint32_t dst, const void* src) {
    asm volatile("cp.async.cg.shared.global [%0], [%1], 16;" :: "r"(dst), "l"(src));
}

// ================= weight transpose -> single fp16: in[R,C] -> out[C,R] ======
__global__ void __launch_bounds__(256) transpose_h(
    const float* __restrict__ in, __half* __restrict__ out, int R, int C)
{
    __shared__ float tile[32][33];
    int tx = threadIdx.x, ty = threadIdx.y;
    int x = blockIdx.x * 32 + tx;
    int y0 = blockIdx.y * 32;
#pragma unroll
    for (int i = ty; i < 32; i += 8)
        tile[i][tx] = in[(size_t)(y0 + i) * C + x];
    __syncthreads();
    int xo = y0 + tx;
    int y1 = blockIdx.x * 32;
#pragma unroll
    for (int i = ty; i < 32; i += 8)
        out[(size_t)(y1 + i) * R + xo] = __float2half_rn(tile[tx][i]);
}

// ================= layernorm =================
__global__ void __launch_bounds__(256) ln_kernel(const float* __restrict__ in,
                                                 const float* __restrict__ gamma,
                                                 const float* __restrict__ beta,
                                                 float* __restrict__ out)
{
    int row = blockIdx.x;
    const float* x = in + (size_t)row * D_MODEL;
    int t = threadIdx.x;
    float v[4];
    float s = 0.f;
#pragma unroll
    for (int i = 0; i < 4; i++) { v[i] = x[i*256 + t]; s += v[i]; }

    __shared__ float red[8];
    __shared__ float bcast;
#pragma unroll
    for (int o = 16; o > 0; o >>= 1) s += __shfl_xor_sync(0xffffffffu, s, o);
    if ((t & 31) == 0) red[t >> 5] = s;
    __syncthreads();
    if (t < 32) {
        float r = (t < 8) ? red[t] : 0.f;
#pragma unroll
        for (int o = 4; o > 0; o >>= 1) r += __shfl_xor_sync(0xffffffffu, r, o);
        if (t == 0) bcast = r;
    }
    __syncthreads();
    float mean = bcast * (1.f / D_MODEL);

    float s2 = 0.f;
#pragma unroll
    for (int i = 0; i < 4; i++) { float d = v[i] - mean; s2 += d*d; }
#pragma unroll
    for (int o = 16; o > 0; o >>= 1) s2 += __shfl_xor_sync(0xffffffffu, s2, o);
    __syncthreads();
    if ((t & 31) == 0) red[t >> 5] = s2;
    __syncthreads();
    if (t < 32) {
        float r = (t < 8) ? red[t] : 0.f;
#pragma unroll
        for (int o = 4; o > 0; o >>= 1) r += __shfl_xor_sync(0xffffffffu, r, o);
        if (t == 0) bcast = r;
    }
    __syncthreads();
    float rstd = rsqrtf(bcast * (1.f / D_MODEL) + 1e-5f);

#pragma unroll
    for (int i = 0; i < 4; i++) {
        int d = i*256 + t;
        out[(size_t)row * D_MODEL + d] = gamma[d] * (v[i] - mean) * rstd + beta[d];
    }
}

// ================= GEMM common epilogue =================
template<int EPI>
__device__ __forceinline__ void gemm_epilogue(
    float acc[2][8][4], const float* bias, const float* res, float* C,
    int m0, int n0, int warp_m, int warp_n, int lane, int N)
{
    int g   = lane >> 2;
    int tig = lane & 3;
#pragma unroll
    for (int mt = 0; mt < 2; mt++) {
#pragma unroll
        for (int nt = 0; nt < 8; nt++) {
            int col = n0 + warp_n * 64 + nt * 8 + 2 * tig;
            int row0 = m0 + warp_m * 32 + mt * 16 + g;
            int row1 = row0 + 8;
            float v00 = acc[mt][nt][0], v01 = acc[mt][nt][1];
            float v10 = acc[mt][nt][2], v11 = acc[mt][nt][3];
            if (EPI != 0) {
                float b0 = bias[col], b1 = bias[col + 1];
                v00 += b0; v01 += b1; v10 += b0; v11 += b1;
            }
            if (EPI == 2) {
                float vv[4] = {v00, v01, v10, v11};
#pragma unroll
                for (int q = 0; q < 4; q++) {
                    float xx = vv[q];
                    float u = 0.7978845608028654f * (xx + 0.044715f * xx * xx * xx);
                    vv[q] = 0.5f * xx * (1.f + tanhf(u));
                }
                v00 = vv[0]; v01 = vv[1]; v10 = vv[2]; v11 = vv[3];
            }
            if (EPI == 1) {
                float2 r0 = *(const float2*)(res + (size_t)row0 * N + col);
                float2 r1 = *(const float2*)(res + (size_t)row1 * N + col);
                v00 += r0.x; v01 += r0.y; v10 += r1.x; v11 += r1.y;
            }
            *(float2*)(C + (size_t)row0 * N + col) = make_float2(v00, v01);
            *(float2*)(C + (size_t)row1 * N + col) = make_float2(v10, v11);
        }
    }
}

// ================= pure fp16 GEMM (1 product) =================
// C = A(fp32,[M,K]) @ Bt^T, Bt single fp16 [N,K].
#define ROW_BYTES  80
#define MAT_BYTES  (128*ROW_BYTES)
#define STAGE1_BYTES (2*MAT_BYTES)       // 20480
#define GEMM1_SMEM   (2*STAGE1_BYTES)    // 40960

template<int EPI>   // 0=plain, 1=bias+res, 2=bias+gelu
__global__ void __launch_bounds__(256) gemm1(
    const float* __restrict__ A, const __half* __restrict__ B,
    const float* __restrict__ bias, const float* __restrict__ res,
    float* __restrict__ C, int M, int N, int K)
{
    extern __shared__ char dynsm[];
    uint32_t sbase = smem_u32(dynsm);

    int t = threadIdx.x;
    int lane = t & 31, wid = t >> 5;
    int warp_m = wid & 3;
    int warp_n = wid >> 2;
    int m0 = blockIdx.y * 128, n0 = blockIdx.x * 128;
    const int NC = K >> 5;

    const float* Ap = A + (size_t)m0 * K;
    const __half* Bp = B + (size_t)n0 * K;

    int lrow  = t >> 3;
    int lcol4 = (t & 7) * 4;
    int brow  = t >> 2;
    int bq    = t & 3;

    float acc[2][8][4];
#pragma unroll
    for (int mt = 0; mt < 2; mt++)
#pragma unroll
        for (int nt = 0; nt < 8; nt++)
#pragma unroll
            for (int r = 0; r < 4; r++) acc[mt][nt][r] = 0.f;

    auto issue_B = [&](int st, int k0) {
#pragma unroll
        for (int i = 0; i < 2; i++) {
            int row = brow + i * 64;
            uint32_t dst = sbase + (uint32_t)(st * STAGE1_BYTES + MAT_BYTES
                                              + row * ROW_BYTES + bq * 16);
            cp16(dst, Bp + (size_t)row * K + k0 + bq * 8);
        }
        asm volatile("cp.async.commit_group;");
    };

    auto sts_A = [&](int st, int row, int col4, float4 v) {
        uint32_t ad = sbase + (uint32_t)(st * STAGE1_BYTES + row * ROW_BYTES + col4 * 2);
        asm volatile("st.shared.v2.b32 [%0], {%1, %2};" :: "r"(ad),
                     "r"(pack_h2(v.x, v.y)), "r"(pack_h2(v.z, v.w)) : "memory");
    };

    auto compute_stage = [&](int st) {
        uint32_t stb = sbase + (uint32_t)st * STAGE1_BYTES;
        uint32_t b_base = stb + MAT_BYTES;
#pragma unroll
        for (int ks = 0; ks < 2; ks++) {
            uint32_t af[2][4];
#pragma unroll
            for (int mt = 0; mt < 2; mt++) {
                int row = warp_m * 32 + mt * 16 + (lane & 15);
                int kcol = ks * 16 + (lane >> 4) * 8;
                uint32_t addr = stb + (uint32_t)(row * ROW_BYTES + kcol * 2);
                LDSM_X4(af[mt][0], af[mt][1], af[mt][2], af[mt][3], addr);
            }
#pragma unroll
            for (int np = 0; np < 4; np++) {
                int nrow = warp_n * 64 + np * 16 + (lane & 7) + ((lane >> 4) << 3);
                int kcol = ks * 16 + ((lane >> 3) & 1) * 8;
                uint32_t addr = b_base + (uint32_t)(nrow * ROW_BYTES + kcol * 2);
                uint32_t bf[4];
                LDSM_X4(bf[0], bf[1], bf[2], bf[3], addr);
#pragma unroll
                for (int mt = 0; mt < 2; mt++) {
                    int nt0 = np * 2;
                    MMA_F16(acc[mt][nt0],   af[mt], bf[0], bf[1]);
                    MMA_F16(acc[mt][nt0+1], af[mt], bf[2], bf[3]);
                }
            }
        }
    };

    issue_B(0, 0);
    {
#pragma unroll
        for (int i = 0; i < 4; i++) {
            int row = lrow + i * 32;
            float4 a4 = *(const float4*)(Ap + (size_t)row * K + lcol4);
            sts_A(0, row, lcol4, a4);
        }
    }
    asm volatile("cp.async.wait_group 0;");
    __syncthreads();

    for (int c = 0; c < NC; c++) {
        int st = c & 1;
        bool has_next = (c + 1 < NC);
        float4 abuf[4];
        if (has_next) {
            int k0 = (c + 1) * 32;
            issue_B(1 - st, k0);
#pragma unroll
            for (int i = 0; i < 4; i++) {
                int row = lrow + i * 32;
                abuf[i] = *(const float4*)(Ap + (size_t)row * K + k0 + lcol4);
            }
        }
        compute_stage(st);
        if (has_next) {
#pragma unroll
            for (int i = 0; i < 4; i++) {
                int row = lrow + i * 32;
                sts_A(1 - st, row, lcol4, abuf[i]);
            }
        }
        asm volatile("cp.async.wait_group 0;");
        __syncthreads();
    }

    gemm_epilogue<EPI>(acc, bias, res, C, m0, n0, warp_m, warp_n, lane, N);
}

// ================= tensor-core flash attention (fp16 2-product, R8 proven) =====
#define AST 144
#define AQ_MAT (128*AST)       // 18432
#define AK_MAT (64*AST)        // 9216
#define ATT_SMEM (AQ_MAT + 4*AK_MAT)   // 55296

__global__ void __launch_bounds__(256) attn_mma(
    const float* __restrict__ QKV, float* __restrict__ O)
{
    extern __shared__ char asmem[];
    uint32_t sb = smem_u32(asmem);
    const uint32_t QF = sb;
    const uint32_t KH = sb + AQ_MAT, KL = KH + AK_MAT;
    const uint32_t VH = KL + AK_MAT, VL = VH + AK_MAT;

    int t = threadIdx.x, lane = t & 31, wid = t >> 5;
    int qt = blockIdx.x, bh = blockIdx.y;
    int b = bh >> 4, h = bh & 15;
    int q0 = qt * 128;

    const float* base = QKV + (size_t)b * SEQ * QKV_W + h * HDIM;
    const float* Qg = base;
    const float* Kg = base + D_MODEL;
    const float* Vg = base + 2 * D_MODEL;

    for (int idx = t; idx < 2048; idx += 256) {
        int r = idx >> 4, c4 = (idx & 15) * 4;
        float4 v = *(const float4*)(Qg + (size_t)(q0 + r) * QKV_W + c4);
        uint32_t ad = QF + (uint32_t)(r * AST + c4 * 2);
        asm volatile("st.shared.v2.b32 [%0], {%1, %2};" :: "r"(ad),
                     "r"(pack_h2(v.x, v.y)), "r"(pack_h2(v.z, v.w)) : "memory");
    }
    __syncthreads();

    uint32_t qf[4][4];
#pragma unroll
    for (int ks = 0; ks < 4; ks++) {
        int row = wid * 16 + (lane & 15);
        int kcol = ks * 16 + (lane >> 4) * 8;
        uint32_t ad = QF + (uint32_t)(row * AST + kcol * 2);
        LDSM_X4(qf[ks][0], qf[ks][1], qf[ks][2], qf[ks][3], ad);
    }

    float oacc[8][4];
#pragma unroll
    for (int nt = 0; nt < 8; nt++)
#pragma unroll
        for (int e = 0; e < 4; e++) oacc[nt][e] = 0.f;
    float mrow[2] = {-1e30f, -1e30f};
    float lrow[2] = {0.f, 0.f};

    int qmax = q0 + wid * 16 + 15;
    int NK = qt * 2 + 2;
    int qrow0 = q0 + wid * 16 + (lane >> 2);
    int lj = 2 * (lane & 3);

    for (int kt = 0; kt < NK; kt++) {
        __syncthreads();
        for (int idx = t; idx < 1024; idx += 256) {
            int r = idx >> 4, c4 = (idx & 15) * 4;
            size_t grow = (size_t)(kt * 64 + r) * QKV_W + c4;
            uint32_t ad = (uint32_t)(r * AST + c4 * 2);
            float4 kv = *(const float4*)(Kg + grow);
            asm volatile("st.shared.v2.b32 [%0], {%1, %2};" :: "r"(KH + ad),
                         "r"(pack_h2(kv.x, kv.y)), "r"(pack_h2(kv.z, kv.w)) : "memory");
            asm volatile("st.shared.v2.b32 [%0], {%1, %2};" :: "r"(KL + ad),
                         "r"(pack_lo_h2(kv.x, kv.y)), "r"(pack_lo_h2(kv.z, kv.w)) : "memory");
            float4 vv = *(const float4*)(Vg + grow);
            asm volatile("st.shared.v2.b32 [%0], {%1, %2};" :: "r"(VH + ad),
                         "r"(pack_h2(vv.x, vv.y)), "r"(pack_h2(vv.z, vv.w)) : "memory");
            asm volatile("st.shared.v2.b32 [%0], {%1, %2};" :: "r"(VL + ad),
                         "r"(pack_lo_h2(vv.x, vv.y)), "r"(pack_lo_h2(vv.z, vv.w)) : "memory");
        }
        __syncthreads();
        if (kt * 64 > qmax) continue;

        float sacc[8][4];
#pragma unroll
        for (int nt = 0; nt < 8; nt++)
#pragma unroll
            for (int e = 0; e < 4; e++) sacc[nt][e] = 0.f;
#pragma unroll
        for (int ks = 0; ks < 4; ks++) {
#pragma unroll
            for (int np = 0; np < 4; np++) {
                int nrow = np * 16 + (lane & 7) + ((lane >> 4) << 3);
                int kcol = ks * 16 + ((lane >> 3) & 1) * 8;
                uint32_t ad = KH + (uint32_t)(nrow * AST + kcol * 2);
                uint32_t bfh[4], bfl[4];
                LDSM_X4(bfh[0], bfh[1], bfh[2], bfh[3], ad);
                LDSM_X4(bfl[0], bfl[1], bfl[2], bfl[3], ad + AK_MAT);
                int nt0 = np * 2;
                MMA_F16(sacc[nt0],   qf[ks], bfh[0], bfh[1]);
                MMA_F16(sacc[nt0+1], qf[ks], bfh[2], bfh[3]);
                MMA_F16(sacc[nt0],   qf[ks], bfl[0], bfl[1]);
                MMA_F16(sacc[nt0+1], qf[ks], bfl[2], bfl[3]);
            }
        }

        bool maskt = (kt >= NK - 2);
#pragma unroll
        for (int nt = 0; nt < 8; nt++) {
            int kgb = kt * 64 + nt * 8 + lj;
#pragma unroll
            for (int e = 0; e < 4; e++) {
                float s = sacc[nt][e] * 0.125f;
                if (maskt) {
                    int kg = kgb + (e & 1);
                    int qg = qrow0 + (e >> 1) * 8;
                    if (kg > qg) s = -1e30f;
                }
                sacc[nt][e] = s;
            }
        }

        float tm0 = -1e30f, tm1 = -1e30f;
#pragma unroll
        for (int nt = 0; nt < 8; nt++) {
            tm0 = fmaxf(tm0, fmaxf(sacc[nt][0], sacc[nt][1]));
            tm1 = fmaxf(tm1, fmaxf(sacc[nt][2], sacc[nt][3]));
        }
        tm0 = fmaxf(tm0, __shfl_xor_sync(0xffffffffu, tm0, 1));
        tm0 = fmaxf(tm0, __shfl_xor_sync(0xffffffffu, tm0, 2));
        tm1 = fmaxf(tm1, __shfl_xor_sync(0xffffffffu, tm1, 1));
        tm1 = fmaxf(tm1, __shfl_xor_sync(0xffffffffu, tm1, 2));
        float mn0 = fmaxf(mrow[0], tm0), mn1 = fmaxf(mrow[1], tm1);
        float al0 = __expf(mrow[0] - mn0), al1 = __expf(mrow[1] - mn1);
        mrow[0] = mn0; mrow[1] = mn1;

        float rs0 = 0.f, rs1 = 0.f;
#pragma unroll
        for (int nt = 0; nt < 8; nt++) {
            float p0 = __expf(sacc[nt][0] - mn0);
            float p1 = __expf(sacc[nt][1] - mn0);
            float p2 = __expf(sacc[nt][2] - mn1);
            float p3 = __expf(sacc[nt][3] - mn1);
            sacc[nt][0] = p0; sacc[nt][1] = p1; sacc[nt][2] = p2; sacc[nt][3] = p3;
            rs0 += p0 + p1; rs1 += p2 + p3;
        }
        rs0 += __shfl_xor_sync(0xffffffffu, rs0, 1);
        rs0 += __shfl_xor_sync(0xffffffffu, rs0, 2);
        rs1 += __shfl_xor_sync(0xffffffffu, rs1, 1);
        rs1 += __shfl_xor_sync(0xffffffffu, rs1, 2);
        lrow[0] = lrow[0] * al0 + rs0;
        lrow[1] = lrow[1] * al1 + rs1;
#pragma unroll
        for (int nt = 0; nt < 8; nt++) {
            oacc[nt][0] *= al0; oacc[nt][1] *= al0;
            oacc[nt][2] *= al1; oacc[nt][3] *= al1;
        }

#pragma unroll
        for (int kt2 = 0; kt2 < 4; kt2++) {
            uint32_t aP[4];
            int n0i = 2 * kt2, n1i = 2 * kt2 + 1;
            aP[0] = pack_h2(sacc[n0i][0], sacc[n0i][1]);
            aP[1] = pack_h2(sacc[n0i][2], sacc[n0i][3]);
            aP[2] = pack_h2(sacc[n1i][0], sacc[n1i][1]);
            aP[3] = pack_h2(sacc[n1i][2], sacc[n1i][3]);
#pragma unroll
            for (int dp = 0; dp < 4; dp++) {
                int krow = kt2 * 16 + ((lane >> 3) & 1) * 8 + (lane & 7);
                int dbyte = dp * 32 + (lane >> 4) * 16;
                uint32_t ad = VH + (uint32_t)(krow * AST + dbyte);
                uint32_t vfh[4], vfl[4];
                LDSM_X4_T(vfh[0], vfh[1], vfh[2], vfh[3], ad);
                LDSM_X4_T(vfl[0], vfl[1], vfl[2], vfl[3], ad + AK_MAT);
                MMA_F16(oacc[2*dp],   aP, vfh[0], vfh[1]);
                MMA_F16(oacc[2*dp+1], aP, vfh[2], vfh[3]);
                MMA_F16(oacc[2*dp],   aP, vfl[0], vfl[1]);
                MMA_F16(oacc[2*dp+1], aP, vfl[2], vfl[3]);
            }
        }
    }

    float inv0 = 1.f / lrow[0], inv1 = 1.f / lrow[1];
    size_t ob = ((size_t)b * SEQ + qrow0) * D_MODEL + h * HDIM;
#pragma unroll
    for (int nt = 0; nt < 8; nt++) {
        int cb = nt * 8 + lj;
        *(float2*)(O + ob + cb) = make_float2(oacc[nt][0] * inv0, oacc[nt][1] * inv0);
        *(float2*)(O + ob + 8 * D_MODEL + cb) = make_float2(oacc[nt][2] * inv1, oacc[nt][3] * inv1);
    }
}

// ================= launch =================
extern "C" void kernel_launch(void* const* d_in, const int* in_sizes, int n_in,
                              void* d_out, int out_size)
{
    (void)in_sizes; (void)n_in; (void)out_size;
    const float* x  = (const float*)d_in[0];
    const float* Wq = (const float*)d_in[1];
    const float* Wk = (const float*)d_in[2];
    const float* Wv = (const float*)d_in[3];
    const float* Wo = (const float*)d_in[4];
    const float* bo = (const float*)d_in[5];
    const float* W1 = (const float*)d_in[6];
    const float* b1 = (const float*)d_in[7];
    const float* W2 = (const float*)d_in[8];
    const float* b2 = (const float*)d_in[9];
    const float* g1 = (const float*)d_in[10];
    const float* s1 = (const float*)d_in[11];
    const float* g2 = (const float*)d_in[12];
    const float* s2 = (const float*)d_in[13];
    float* out = (float*)d_out;

    float *ln, *qkv, *ctx, *h, *f1;
    __half *wqkvT, *woT, *w1T, *w2T;
    cudaGetSymbolAddress((void**)&ln,    g_ln);
    cudaGetSymbolAddress((void**)&qkv,   g_qkv);
    cudaGetSymbolAddress((void**)&ctx,   g_ctx);
    cudaGetSymbolAddress((void**)&h,     g_h);
    cudaGetSymbolAddress((void**)&f1,    g_f1);
    cudaGetSymbolAddress((void**)&wqkvT, g_wqkvT);
    cudaGetSymbolAddress((void**)&woT,   g_woT);
    cudaGetSymbolAddress((void**)&w1T,   g_w1T);
    cudaGetSymbolAddress((void**)&w2T,   g_w2T);

    cudaFuncSetAttribute(gemm1<0>, cudaFuncAttributeMaxDynamicSharedMemorySize, GEMM1_SMEM);
    cudaFuncSetAttribute(gemm1<1>, cudaFuncAttributeMaxDynamicSharedMemorySize, GEMM1_SMEM);
    cudaFuncSetAttribute(gemm1<2>, cudaFuncAttributeMaxDynamicSharedMemorySize, GEMM1_SMEM);
    cudaFuncSetAttribute(attn_mma, cudaFuncAttributeMaxDynamicSharedMemorySize, ATT_SMEM);

    dim3 tb(32, 8);
    transpose_h<<<dim3(D_MODEL/32, D_MODEL/32), tb>>>(Wq, wqkvT,                        D_MODEL, D_MODEL);
    transpose_h<<<dim3(D_MODEL/32, D_MODEL/32), tb>>>(Wk, wqkvT + 1024*(size_t)D_MODEL, D_MODEL, D_MODEL);
    transpose_h<<<dim3(D_MODEL/32, D_MODEL/32), tb>>>(Wv, wqkvT + 2048*(size_t)D_MODEL, D_MODEL, D_MODEL);
    transpose_h<<<dim3(D_MODEL/32, D_MODEL/32), tb>>>(Wo, woT, D_MODEL, D_MODEL);
    transpose_h<<<dim3(DFF/32,     D_MODEL/32), tb>>>(W1, w1T, D_MODEL, DFF);
    transpose_h<<<dim3(D_MODEL/32, DFF/32),     tb>>>(W2, w2T, DFF, D_MODEL);

    // 1. ln1 = LN(x)
    ln_kernel<<<NTOK, 256>>>(x, g1, s1, ln);
    // 2. qkv = ln1 @ [Wq|Wk|Wv]
    gemm1<0><<<dim3(QKV_W/128, NTOK/128), 256, GEMM1_SMEM>>>(ln, wqkvT, nullptr, nullptr, qkv, NTOK, QKV_W, D_MODEL);
    // 3. causal attention
    attn_mma<<<dim3(SEQ/128, BATCH*NHEADS), 256, ATT_SMEM>>>(qkv, ctx);
    // 4. h = x + ctx @ Wo + bo
    gemm1<1><<<dim3(D_MODEL/128, NTOK/128), 256, GEMM1_SMEM>>>(ctx, woT, bo, x, h, NTOK, D_MODEL, D_MODEL);
    // 5. ln2 = LN(h)
    ln_kernel<<<NTOK, 256>>>(h, g2, s2, ln);
    // 6. f1 = gelu(ln2 @ W1 + b1)
    gemm1<2><<<dim3(DFF/128, NTOK/128), 256, GEMM1_SMEM>>>(ln, w1T, b1, nullptr, f1, NTOK, DFF, D_MODEL);
    // 7. out = h + f1 @ W2 + b2
    gemm1<1><<<dim3(D_MODEL/128, NTOK/128), 256, GEMM1_SMEM>>>(f1, w2T, b2, h, out, NTOK, D_MODEL, DFF);
}